// round 6
// baseline (speedup 1.0000x reference)
#include <cuda_runtime.h>
#include <cuda_fp16.h>
#include <math.h>
#include <stdint.h>

#define BB 8
#define HH 128
#define WW 128
#define CC 64

// ---------------- scratch (allocation-free rule) ----------------
__device__ __align__(16) __half g_xh[BB*HH*WW*CC];      // NHWC x fp16 (gather)
__device__ __align__(16) uint2  g_wfragB[9*8*4*32];     // mma B-fragments fp16
__device__ __align__(16) float  g_wcoef[9*CC*4];        // [tap][c][{sin,cos,str,whl}]
__device__ __align__(16) float4 g_coef[BB*HH*WW];       // (sin, cos, wr*r, wr)

// ---------------- smem layout of k_main (dynamic, bytes) ----------------
#define A_STRIDE 144
#define SM_A0   0
#define SM_A1   18432
#define SM_B0   36864          // [3][8192] triple-buffered B ring
#define SM_SSB  61440          // int4[2][128]
#define SM_SSW  65536          // uint2[2][128]
#define SMEM_REQ 67584

// ---------------- helpers ----------------
__device__ __forceinline__ uint32_t smem_u32(const void* p) {
    uint32_t a;
    asm("{ .reg .u64 t; cvta.to.shared.u64 t, %1; cvt.u32.u64 %0, t; }" : "=r"(a) : "l"(p));
    return a;
}
__device__ __forceinline__ void ldsm_x4(uint32_t* r, uint32_t addr) {
    asm volatile("ldmatrix.sync.aligned.m8n8.x4.shared.b16 {%0,%1,%2,%3}, [%4];"
                 : "=r"(r[0]), "=r"(r[1]), "=r"(r[2]), "=r"(r[3]) : "r"(addr));
}
__device__ __forceinline__ void mma16816(float* d, const uint32_t* a, uint2 b) {
    asm volatile(
        "mma.sync.aligned.m16n8k16.row.col.f32.f16.f16.f32 "
        "{%0,%1,%2,%3}, {%4,%5,%6,%7}, {%8,%9}, {%0,%1,%2,%3};"
        : "+f"(d[0]), "+f"(d[1]), "+f"(d[2]), "+f"(d[3])
        : "r"(a[0]), "r"(a[1]), "r"(a[2]), "r"(a[3]), "r"(b.x), "r"(b.y));
}
__device__ __forceinline__ void cp16(uint32_t smem_dst, const void* gsrc) {
    asm volatile("cp.async.ca.shared.global [%0], [%1], 16;"
                 :: "r"(smem_dst), "l"(gsrc) : "memory");
}

// ---------------------------------------------------------------------------
// K0: weight prep — fp16 B-fragments for mma + coef weights
// ---------------------------------------------------------------------------
__global__ void k_wprep(const float* __restrict__ wmain,
                        const float* __restrict__ wrot,
                        const float* __restrict__ wstr,
                        const float* __restrict__ wwhl) {
    int idx = blockIdx.x * 256 + threadIdx.x;
    if (idx < 9 * CC * CC) {
        int o = idx % CC;
        int c = (idx / CC) % CC;
        int k = idx / (CC * CC);
        float w = wmain[(o * CC + c) * 9 + k];
        int j = o >> 3, lane_n = o & 7;
        int q = c >> 4, kk = c & 15;
        int reg = kk >> 3, r = kk & 7;
        int lane = lane_n * 4 + (r >> 1);
        int halfsel = r & 1;
        __half* dst = (__half*)g_wfragB;
        dst[(((size_t)(k * 8 + j) * 4 + q) * 32 + lane) * 4 + reg * 2 + halfsel] = __float2half(w);
    }
    if (idx < 9 * CC * 4) {
        int o   = idx & 3;
        int c   = (idx >> 2) % CC;
        int pos = idx / (CC * 4);
        float v;
        if (o == 0)      v = wrot[(0 * CC + c) * 9 + pos];
        else if (o == 1) v = wrot[(1 * CC + c) * 9 + pos];
        else if (o == 2) v = wstr[c * 9 + pos];
        else             v = wwhl[c * 9 + pos];
        g_wcoef[idx] = v;
    }
}

// ---------------------------------------------------------------------------
// K1: NCHW -> NHWC fp16 transpose
// ---------------------------------------------------------------------------
__global__ void k_transpose(const float* __restrict__ x) {
    __shared__ float sm[32][33];
    int b  = blockIdx.z;
    int c0 = blockIdx.y * 32;
    int s0 = blockIdx.x * 32;
    int tx = threadIdx.x, ty = threadIdx.y;   // 32 x 8
#pragma unroll
    for (int i = 0; i < 4; i++) {
        int c = c0 + ty + i * 8;
        sm[ty + i * 8][tx] = x[(b * CC + c) * (HH * WW) + s0 + tx];
    }
    __syncthreads();
#pragma unroll
    for (int i = 0; i < 4; i++) {
        int s = s0 + ty + i * 8;
        g_xh[(size_t)(b * (HH * WW) + s) * CC + c0 + tx] = __float2half(sm[tx][ty + i * 8]);
    }
}

// ---------------------------------------------------------------------------
// K2: coefficient convs (fp32, straight from NCHW x) -> g_coef
// ---------------------------------------------------------------------------
__global__ void __launch_bounds__(256) k_coef(const float* __restrict__ x,
                                              const float* __restrict__ brot,
                                              const float* __restrict__ bstr,
                                              const float* __restrict__ bwhl) {
    __shared__ float4 swc[CC * 9];    // [c][tap]
    __shared__ float4 red[256];

    const int t  = threadIdx.x;
    const int p  = t & 127;
    const int hf = t >> 7;
    const int bh = blockIdx.x;
    const int b  = bh >> 7;
    const int h  = bh & 127;

    {
        const float4* gw4 = (const float4*)g_wcoef;
        for (int i = t; i < CC * 9; i += 256) {
            int c = i / 9, tap = i - c * 9;
            swc[i] = gw4[tap * 64 + c];
        }
    }
    __syncthreads();

    float a0 = 0.f, a1 = 0.f, a2 = 0.f, a3 = 0.f;
    const int c0 = hf * 32;
    const float* xb = x + ((size_t)b * CC + c0) * (HH * WW);
#pragma unroll 4
    for (int ci = 0; ci < 32; ci++) {
        const float* xc = xb + (size_t)ci * (HH * WW);
        const float4* wc = swc + (c0 + ci) * 9;
#pragma unroll
        for (int dy = 0; dy < 3; dy++) {
            int y = h + dy - 1;
            if ((unsigned)y >= HH) continue;
            const float* row = xc + y * WW;
            float xm = (p > 0)       ? row[p - 1] : 0.f;
            float x0 = row[p];
            float xp = (p < WW - 1)  ? row[p + 1] : 0.f;
            float4 wA = wc[dy * 3 + 0];
            float4 wB = wc[dy * 3 + 1];
            float4 wC = wc[dy * 3 + 2];
            a0 += xm * wA.x + x0 * wB.x + xp * wC.x;
            a1 += xm * wA.y + x0 * wB.y + xp * wC.y;
            a2 += xm * wA.z + x0 * wB.z + xp * wC.z;
            a3 += xm * wA.w + x0 * wB.w + xp * wC.w;
        }
    }
    red[t] = make_float4(a0, a1, a2, a3);
    __syncthreads();
    if (t < 128) {
        float4 u = red[t], v = red[t + 128];
        float s = u.x + v.x + brot[0];
        float c = u.y + v.y + brot[1];
        float n = sqrtf(s * s + c * c + 1e-6f);
        s /= n; c /= n;
        float r  = tanhf(u.z + v.z + bstr[0]) * 1.25f + 1.75f;
        float wl = tanhf(u.w + v.w + bwhl[0]) * 1.0f + 2.0f;
        g_coef[bh * WW + t] = make_float4(s, c, wl * r, wl);
    }
}

// ---------------------------------------------------------------------------
// K3: deform gather (fp16) + mma.sync GEMM, 1 sync/tap, cp.async B ring
// CTA = one (b,h) row (128 px), 256 threads / 8 warps, 3 CTAs/SM.
// ---------------------------------------------------------------------------
__global__ void __launch_bounds__(256, 3) k_main(float* __restrict__ out) {
    extern __shared__ __align__(16) char smc[];
    int4*  ssb = (int4*)(smc + SM_SSB);    // [2][128]
    uint2* ssw = (uint2*)(smc + SM_SSW);   // [2][128]

    const int t    = threadIdx.x;
    const int wid  = t >> 5;
    const int lane = t & 31;
    const int bh   = blockIdx.x;
    const int b    = bh >> 7;
    const int h    = bh & 127;
    const char* xhimg = (const char*)(g_xh + (size_t)b * HH * WW * CC);

    float4 cf;
    if (t < 128) cf = g_coef[bh * WW + t];

    auto coords = [&](int k, int bf) {
        if (t >= 128) return;
        int kd3 = (k * 11) >> 5;
        float ky = (float)(kd3 - 1);
        float kx = (float)(k - 3 * kd3 - 1);
        float o0 = ky * cf.z;
        float o1 = kx * cf.w;
        float py = (float)h + cf.y * o0 + cf.x * o1;
        float px = (float)t - cf.x * o0 + cf.y * o1;
        float yf = floorf(py), xf = floorf(px);
        float ly = py - yf, lx = px - xf;
        int y0 = (int)yf, x0 = (int)xf;
        int y1 = y0 + 1,  x1 = x0 + 1;
        float w00 = (1.f - ly) * (1.f - lx);
        float w01 = (1.f - ly) * lx;
        float w10 = ly * (1.f - lx);
        float w11 = ly * lx;
        float vy0 = (y0 >= 0 && y0 < HH) ? 1.f : 0.f;
        float vy1 = (y1 >= 0 && y1 < HH) ? 1.f : 0.f;
        float vx0 = (x0 >= 0 && x0 < WW) ? 1.f : 0.f;
        float vx1 = (x1 >= 0 && x1 < WW) ? 1.f : 0.f;
        w00 *= vy0 * vx0; w01 *= vy0 * vx1;
        w10 *= vy1 * vx0; w11 *= vy1 * vx1;
        int yc0 = min(max(y0, 0), HH - 1);
        int yc1 = min(max(y1, 0), HH - 1);
        int xc0 = min(max(x0, 0), WW - 1);
        int xc1 = min(max(x1, 0), WW - 1);
        int4 bs;   // BYTE offsets into fp16 image (row = 128 B)
        bs.x = (yc0 * WW + xc0) << 7;
        bs.y = (yc0 * WW + xc1) << 7;
        bs.z = (yc1 * WW + xc0) << 7;
        bs.w = (yc1 * WW + xc1) << 7;
        ssb[bf * 128 + t] = bs;
        uint32_t wlo, whi;
        asm("cvt.rn.f16x2.f32 %0, %1, %2;" : "=r"(wlo) : "f"(w01), "f"(w00));
        asm("cvt.rn.f16x2.f32 %0, %1, %2;" : "=r"(whi) : "f"(w11), "f"(w10));
        ssw[bf * 128 + t] = make_uint2(wlo, whi);
    };

    const uint32_t smB_u = smem_u32(smc + SM_B0);

    // prime: cp.async B(0) -> ring buf 0
    {
        const char* src = (const char*)g_wfragB;
        cp16(smB_u + t * 16, src + t * 16);
        cp16(smB_u + (t + 256) * 16, src + (t + 256) * 16);
        asm volatile("cp.async.commit_group;" ::: "memory");
    }
    coords(0, 0);
    __syncthreads();   // ssb0/ssw0 ready

    const uint32_t smA_u = smem_u32(smc);
    const int m0 = wid * 16;
    const uint32_t ldsm_lane_off = (uint32_t)((lane & 15)) * A_STRIDE + ((lane >> 4) << 4);

    float acc[8][4];
#pragma unroll
    for (int j = 0; j < 8; j++)
#pragma unroll
        for (int i = 0; i < 4; i++) acc[j][i] = 0.f;

    const int lc8  = t & 7;    // channel octet (16 B fp16)
    const int gg32 = t >> 3;   // 0..31
    int rb = 0;                // ring slot of B(k)

#pragma unroll 1
    for (int k = 0; k < 9; k++) {
        const int bf = k & 1;

        // ---- gather tap k (fp16) into A[bf] ----
        {
            const int4*  sbp = ssb + bf * 128;
            const uint2* swp = ssw + bf * 128;
            char* Ab = smc + (bf ? SM_A1 : SM_A0);
#pragma unroll
            for (int it = 0; it < 4; it++) {
                int p = it * 32 + gg32;
                int4  bs = sbp[p];
                uint2 wv = swp[p];
                uint32_t u00 = __byte_perm(wv.x, 0, 0x1010);
                uint32_t u01 = __byte_perm(wv.x, 0, 0x3232);
                uint32_t u10 = __byte_perm(wv.y, 0, 0x1010);
                uint32_t u11 = __byte_perm(wv.y, 0, 0x3232);
                __half2 H00 = *(__half2*)&u00, H01 = *(__half2*)&u01;
                __half2 H10 = *(__half2*)&u10, H11 = *(__half2*)&u11;
                uint4 v0 = *(const uint4*)(xhimg + bs.x + lc8 * 16);
                uint4 v1 = *(const uint4*)(xhimg + bs.y + lc8 * 16);
                uint4 v2 = *(const uint4*)(xhimg + bs.z + lc8 * 16);
                uint4 v3 = *(const uint4*)(xhimg + bs.w + lc8 * 16);
                uint4 gv;
                {
                    __half2 a;
                    a = __hmul2(*(__half2*)&v0.x, H00);
                    a = __hfma2(*(__half2*)&v1.x, H01, a);
                    a = __hfma2(*(__half2*)&v2.x, H10, a);
                    a = __hfma2(*(__half2*)&v3.x, H11, a);
                    gv.x = *(uint32_t*)&a;
                    a = __hmul2(*(__half2*)&v0.y, H00);
                    a = __hfma2(*(__half2*)&v1.y, H01, a);
                    a = __hfma2(*(__half2*)&v2.y, H10, a);
                    a = __hfma2(*(__half2*)&v3.y, H11, a);
                    gv.y = *(uint32_t*)&a;
                    a = __hmul2(*(__half2*)&v0.z, H00);
                    a = __hfma2(*(__half2*)&v1.z, H01, a);
                    a = __hfma2(*(__half2*)&v2.z, H10, a);
                    a = __hfma2(*(__half2*)&v3.z, H11, a);
                    gv.z = *(uint32_t*)&a;
                    a = __hmul2(*(__half2*)&v0.w, H00);
                    a = __hfma2(*(__half2*)&v1.w, H01, a);
                    a = __hfma2(*(__half2*)&v2.w, H10, a);
                    a = __hfma2(*(__half2*)&v3.w, H11, a);
                    gv.w = *(uint32_t*)&a;
                }
                *(uint4*)(Ab + p * A_STRIDE + lc8 * 16) = gv;
            }
        }

        // ---- coords for tap k+1 ----
        if (k < 8) coords(k + 1, bf ^ 1);

        // ---- cp.async B(k+1) into ring slot (rb+1)%3 (not read by anyone now) ----
        if (k < 8) {
            int nb = rb + 1; if (nb == 3) nb = 0;
            const char* src = (const char*)(g_wfragB + (size_t)(k + 1) * 1024);
            uint32_t dstb = smB_u + (uint32_t)nb * 8192;
            cp16(dstb + t * 16, src + t * 16);
            cp16(dstb + (t + 256) * 16, src + (t + 256) * 16);
        }
        asm volatile("cp.async.commit_group;" ::: "memory");
        asm volatile("cp.async.wait_group 1;" ::: "memory");   // B(k) complete
        __syncthreads();   // A[bf] + all threads' B(k) waits done; everyone past MMA(k-1)

        // ---- tensor phase: 4 ldmatrix.x4 (A) + B LDS + 32 HMMA ----
        {
            const uint32_t abase = smA_u + (uint32_t)(bf ? SM_A1 : SM_A0) +
                                   (uint32_t)m0 * A_STRIDE + ldsm_lane_off;
            uint32_t a[4][4];
#pragma unroll
            for (int q = 0; q < 4; q++) ldsm_x4(a[q], abase + q * 32);
            const uint2* bp = (const uint2*)(smc + SM_B0 + rb * 8192) + lane;
#pragma unroll
            for (int j = 0; j < 8; j++) {
                uint2 bfr[4];
#pragma unroll
                for (int q = 0; q < 4; q++) bfr[q] = bp[(j * 4 + q) * 32];
#pragma unroll
                for (int q = 0; q < 4; q++) mma16816(acc[j], a[q], bfr[q]);
            }
        }
        rb = rb + 1; if (rb == 3) rb = 0;
    }

    // ===================== epilogue: smem-staged coalesced store =====================
    __syncthreads();
    {
        float* sout = (float*)smc;   // [64][132] floats = 33792 B (overlaps A)
        int pxa = m0 + (lane >> 2);
#pragma unroll
        for (int j = 0; j < 8; j++) {
            int o = j * 8 + (lane & 3) * 2;
            sout[o * 132 + pxa]           = acc[j][0];
            sout[(o + 1) * 132 + pxa]     = acc[j][1];
            sout[o * 132 + pxa + 8]       = acc[j][2];
            sout[(o + 1) * 132 + pxa + 8] = acc[j][3];
        }
        __syncthreads();
#pragma unroll
        for (int it = 0; it < 8; it++) {
            int idx = it * 256 + t;
            int o = idx >> 5, pxq = idx & 31;
            float4 vv = *(const float4*)(sout + o * 132 + pxq * 4);
            *(float4*)(out + ((size_t)(b * CC + o) * HH + h) * WW + pxq * 4) = vv;
        }
    }
}

// ---------------------------------------------------------------------------
extern "C" void kernel_launch(void* const* d_in, const int* in_sizes, int n_in,
                              void* d_out, int out_size) {
    const float* x     = (const float*)d_in[0];
    const float* wmain = (const float*)d_in[1];
    const float* wrot  = (const float*)d_in[2];
    const float* brot  = (const float*)d_in[3];
    const float* wstr  = (const float*)d_in[4];
    const float* bstr  = (const float*)d_in[5];
    const float* wwhl  = (const float*)d_in[6];
    const float* bwhl  = (const float*)d_in[7];
    float* out = (float*)d_out;

    cudaFuncSetAttribute(k_main, cudaFuncAttributeMaxDynamicSharedMemorySize, SMEM_REQ);

    k_wprep<<<144, 256>>>(wmain, wrot, wstr, wwhl);
    k_transpose<<<dim3(512, 2, 8), dim3(32, 8)>>>(x);
    k_coef<<<BB * HH, 256>>>(x, brot, bstr, bwhl);
    k_main<<<BB * HH, 256, SMEM_REQ>>>(out);
}

// round 7
// speedup vs baseline: 1.4824x; 1.4824x over previous
#include <cuda_runtime.h>
#include <cuda_fp16.h>
#include <math.h>
#include <stdint.h>

#define BB 8
#define HH 128
#define WW 128
#define CC 64

// ---------------- scratch (allocation-free rule) ----------------
__device__ __align__(16) __half g_xh[BB*HH*WW*CC];      // NHWC x fp16 (gather)
__device__ __align__(16) uint2  g_wfragB[9*8*4*32];     // mma B-fragments fp16
__device__ __align__(16) float  g_wcoef[9*CC*4];        // [tap][c][{sin,cos,str,whl}]
__device__ __align__(16) float4 g_coef[BB*HH*WW];       // (sin, cos, wr*r, wr)

// ---------------- smem layout of k_main (dynamic, bytes) ----------------
#define A_STRIDE 144
#define SM_A0   0
#define SM_A1   18432
#define SM_B0   36864          // [3][8192] triple-buffered B ring
#define SM_SSB  61440          // int4[2][128]
#define SM_SSW  65536          // uint2[2][128]
#define SMEM_REQ 67584

// ---------------- helpers ----------------
__device__ __forceinline__ uint32_t smem_u32(const void* p) {
    uint32_t a;
    asm("{ .reg .u64 t; cvta.to.shared.u64 t, %1; cvt.u32.u64 %0, t; }" : "=r"(a) : "l"(p));
    return a;
}
__device__ __forceinline__ void ldsm_x4(uint32_t* r, uint32_t addr) {
    asm volatile("ldmatrix.sync.aligned.m8n8.x4.shared.b16 {%0,%1,%2,%3}, [%4];"
                 : "=r"(r[0]), "=r"(r[1]), "=r"(r[2]), "=r"(r[3]) : "r"(addr));
}
__device__ __forceinline__ void mma16816(float* d, const uint32_t* a, uint2 b) {
    asm volatile(
        "mma.sync.aligned.m16n8k16.row.col.f32.f16.f16.f32 "
        "{%0,%1,%2,%3}, {%4,%5,%6,%7}, {%8,%9}, {%0,%1,%2,%3};"
        : "+f"(d[0]), "+f"(d[1]), "+f"(d[2]), "+f"(d[3])
        : "r"(a[0]), "r"(a[1]), "r"(a[2]), "r"(a[3]), "r"(b.x), "r"(b.y));
}
__device__ __forceinline__ void cp16(uint32_t smem_dst, const void* gsrc) {
    asm volatile("cp.async.ca.shared.global [%0], [%1], 16;"
                 :: "r"(smem_dst), "l"(gsrc) : "memory");
}

// ---------------------------------------------------------------------------
// K0: weight prep — fp16 B-fragments for mma + coef weights
// ---------------------------------------------------------------------------
__global__ void k_wprep(const float* __restrict__ wmain,
                        const float* __restrict__ wrot,
                        const float* __restrict__ wstr,
                        const float* __restrict__ wwhl) {
    int idx = blockIdx.x * 256 + threadIdx.x;
    if (idx < 9 * CC * CC) {
        int o = idx % CC;
        int c = (idx / CC) % CC;
        int k = idx / (CC * CC);
        float w = wmain[(o * CC + c) * 9 + k];
        int j = o >> 3, lane_n = o & 7;
        int q = c >> 4, kk = c & 15;
        int reg = kk >> 3, r = kk & 7;
        int lane = lane_n * 4 + (r >> 1);
        int halfsel = r & 1;
        __half* dst = (__half*)g_wfragB;
        dst[(((size_t)(k * 8 + j) * 4 + q) * 32 + lane) * 4 + reg * 2 + halfsel] = __float2half(w);
    }
    if (idx < 9 * CC * 4) {
        int o   = idx & 3;
        int c   = (idx >> 2) % CC;
        int pos = idx / (CC * 4);
        float v;
        if (o == 0)      v = wrot[(0 * CC + c) * 9 + pos];
        else if (o == 1) v = wrot[(1 * CC + c) * 9 + pos];
        else if (o == 2) v = wstr[c * 9 + pos];
        else             v = wwhl[c * 9 + pos];
        g_wcoef[idx] = v;
    }
}

// ---------------------------------------------------------------------------
// K1: NCHW -> NHWC fp16 transpose
// ---------------------------------------------------------------------------
__global__ void k_transpose(const float* __restrict__ x) {
    __shared__ float sm[32][33];
    int b  = blockIdx.z;
    int c0 = blockIdx.y * 32;
    int s0 = blockIdx.x * 32;
    int tx = threadIdx.x, ty = threadIdx.y;   // 32 x 8
#pragma unroll
    for (int i = 0; i < 4; i++) {
        int c = c0 + ty + i * 8;
        sm[ty + i * 8][tx] = x[(b * CC + c) * (HH * WW) + s0 + tx];
    }
    __syncthreads();
#pragma unroll
    for (int i = 0; i < 4; i++) {
        int s = s0 + ty + i * 8;
        g_xh[(size_t)(b * (HH * WW) + s) * CC + c0 + tx] = __float2half(sm[tx][ty + i * 8]);
    }
}

// ---------------------------------------------------------------------------
// K2: coefficient convs (fp32, straight from NCHW x) -> g_coef
// ---------------------------------------------------------------------------
__global__ void __launch_bounds__(256) k_coef(const float* __restrict__ x,
                                              const float* __restrict__ brot,
                                              const float* __restrict__ bstr,
                                              const float* __restrict__ bwhl) {
    __shared__ float4 swc[CC * 9];    // [c][tap]
    __shared__ float4 red[256];

    const int t  = threadIdx.x;
    const int p  = t & 127;
    const int hf = t >> 7;
    const int bh = blockIdx.x;
    const int b  = bh >> 7;
    const int h  = bh & 127;

    {
        const float4* gw4 = (const float4*)g_wcoef;
        for (int i = t; i < CC * 9; i += 256) {
            int c = i / 9, tap = i - c * 9;
            swc[i] = gw4[tap * 64 + c];
        }
    }
    __syncthreads();

    float a0 = 0.f, a1 = 0.f, a2 = 0.f, a3 = 0.f;
    const int c0 = hf * 32;
    const float* xb = x + ((size_t)b * CC + c0) * (HH * WW);
#pragma unroll 4
    for (int ci = 0; ci < 32; ci++) {
        const float* xc = xb + (size_t)ci * (HH * WW);
        const float4* wc = swc + (c0 + ci) * 9;
#pragma unroll
        for (int dy = 0; dy < 3; dy++) {
            int y = h + dy - 1;
            if ((unsigned)y >= HH) continue;
            const float* row = xc + y * WW;
            float xm = (p > 0)       ? row[p - 1] : 0.f;
            float x0 = row[p];
            float xp = (p < WW - 1)  ? row[p + 1] : 0.f;
            float4 wA = wc[dy * 3 + 0];
            float4 wB = wc[dy * 3 + 1];
            float4 wC = wc[dy * 3 + 2];
            a0 += xm * wA.x + x0 * wB.x + xp * wC.x;
            a1 += xm * wA.y + x0 * wB.y + xp * wC.y;
            a2 += xm * wA.z + x0 * wB.z + xp * wC.z;
            a3 += xm * wA.w + x0 * wB.w + xp * wC.w;
        }
    }
    red[t] = make_float4(a0, a1, a2, a3);
    __syncthreads();
    if (t < 128) {
        float4 u = red[t], v = red[t + 128];
        float s = u.x + v.x + brot[0];
        float c = u.y + v.y + brot[1];
        float n = sqrtf(s * s + c * c + 1e-6f);
        s /= n; c /= n;
        float r  = tanhf(u.z + v.z + bstr[0]) * 1.25f + 1.75f;
        float wl = tanhf(u.w + v.w + bwhl[0]) * 1.0f + 2.0f;
        g_coef[bh * WW + t] = make_float4(s, c, wl * r, wl);
    }
}

// ---------------------------------------------------------------------------
// K3: deform gather (fp16) + mma.sync GEMM
// CTA = one (b,h) row (128 px), 512 threads / 16 warps, 2 CTAs/SM.
// Warp w: M-tile (w&7)*16, N-half (w>>3)*32 -> acc = 16 regs/thread.
// ---------------------------------------------------------------------------
__global__ void __launch_bounds__(512, 2) k_main(float* __restrict__ out) {
    extern __shared__ __align__(16) char smc[];
    int4*  ssb = (int4*)(smc + SM_SSB);    // [2][128]
    uint2* ssw = (uint2*)(smc + SM_SSW);   // [2][128]

    const int t    = threadIdx.x;
    const int wid  = t >> 5;
    const int lane = t & 31;
    const int bh   = blockIdx.x;
    const int b    = bh >> 7;
    const int h    = bh & 127;
    const char* xhimg = (const char*)(g_xh + (size_t)b * HH * WW * CC);

    float4 cf;
    if (t < 128) cf = g_coef[bh * WW + t];

    auto coords = [&](int k, int bf) {
        if (t >= 128) return;
        int kd3 = (k * 11) >> 5;
        float ky = (float)(kd3 - 1);
        float kx = (float)(k - 3 * kd3 - 1);
        float o0 = ky * cf.z;
        float o1 = kx * cf.w;
        float py = (float)h + cf.y * o0 + cf.x * o1;
        float px = (float)t - cf.x * o0 + cf.y * o1;
        float yf = floorf(py), xf = floorf(px);
        float ly = py - yf, lx = px - xf;
        int y0 = (int)yf, x0 = (int)xf;
        int y1 = y0 + 1,  x1 = x0 + 1;
        float w00 = (1.f - ly) * (1.f - lx);
        float w01 = (1.f - ly) * lx;
        float w10 = ly * (1.f - lx);
        float w11 = ly * lx;
        float vy0 = (y0 >= 0 && y0 < HH) ? 1.f : 0.f;
        float vy1 = (y1 >= 0 && y1 < HH) ? 1.f : 0.f;
        float vx0 = (x0 >= 0 && x0 < WW) ? 1.f : 0.f;
        float vx1 = (x1 >= 0 && x1 < WW) ? 1.f : 0.f;
        w00 *= vy0 * vx0; w01 *= vy0 * vx1;
        w10 *= vy1 * vx0; w11 *= vy1 * vx1;
        int yc0 = min(max(y0, 0), HH - 1);
        int yc1 = min(max(y1, 0), HH - 1);
        int xc0 = min(max(x0, 0), WW - 1);
        int xc1 = min(max(x1, 0), WW - 1);
        int4 bs;   // BYTE offsets into fp16 image (row = 128 B)
        bs.x = (yc0 * WW + xc0) << 7;
        bs.y = (yc0 * WW + xc1) << 7;
        bs.z = (yc1 * WW + xc0) << 7;
        bs.w = (yc1 * WW + xc1) << 7;
        ssb[bf * 128 + t] = bs;
        uint32_t wlo, whi;
        asm("cvt.rn.f16x2.f32 %0, %1, %2;" : "=r"(wlo) : "f"(w01), "f"(w00));
        asm("cvt.rn.f16x2.f32 %0, %1, %2;" : "=r"(whi) : "f"(w11), "f"(w10));
        ssw[bf * 128 + t] = make_uint2(wlo, whi);
    };

    const uint32_t smB_u = smem_u32(smc + SM_B0);

    // prime: cp.async B(0) -> ring buf 0 (8 KB = 512 x 16 B)
    {
        const char* src = (const char*)g_wfragB;
        cp16(smB_u + t * 16, src + t * 16);
        asm volatile("cp.async.commit_group;" ::: "memory");
    }
    coords(0, 0);
    __syncthreads();   // ssb0/ssw0 ready

    const uint32_t smA_u = smem_u32(smc);
    const int m0    = (wid & 7) * 16;
    const int jbase = (wid >> 3) * 4;
    const uint32_t ldsm_lane_off = (uint32_t)((lane & 15)) * A_STRIDE + ((lane >> 4) << 4);

    float acc[4][4];
#pragma unroll
    for (int j = 0; j < 4; j++)
#pragma unroll
        for (int i = 0; i < 4; i++) acc[j][i] = 0.f;

    const int lc8  = t & 7;    // channel octet (16 B fp16)
    const int gg64 = t >> 3;   // 0..63
    int rb = 0;                // ring slot of B(k)

#pragma unroll 1
    for (int k = 0; k < 9; k++) {
        const int bf = k & 1;

        // ---- gather tap k (fp16) into A[bf]: 2 pixels/thread ----
        {
            const int4*  sbp = ssb + bf * 128;
            const uint2* swp = ssw + bf * 128;
            char* Ab = smc + (bf ? SM_A1 : SM_A0);
#pragma unroll
            for (int it = 0; it < 2; it++) {
                int p = it * 64 + gg64;
                int4  bs = sbp[p];
                uint2 wv = swp[p];
                uint32_t u00 = __byte_perm(wv.x, 0, 0x1010);
                uint32_t u01 = __byte_perm(wv.x, 0, 0x3232);
                uint32_t u10 = __byte_perm(wv.y, 0, 0x1010);
                uint32_t u11 = __byte_perm(wv.y, 0, 0x3232);
                __half2 H00 = *(__half2*)&u00, H01 = *(__half2*)&u01;
                __half2 H10 = *(__half2*)&u10, H11 = *(__half2*)&u11;
                uint4 v0 = *(const uint4*)(xhimg + bs.x + lc8 * 16);
                uint4 v1 = *(const uint4*)(xhimg + bs.y + lc8 * 16);
                uint4 v2 = *(const uint4*)(xhimg + bs.z + lc8 * 16);
                uint4 v3 = *(const uint4*)(xhimg + bs.w + lc8 * 16);
                uint4 gv;
                {
                    __half2 a;
                    a = __hmul2(*(__half2*)&v0.x, H00);
                    a = __hfma2(*(__half2*)&v1.x, H01, a);
                    a = __hfma2(*(__half2*)&v2.x, H10, a);
                    a = __hfma2(*(__half2*)&v3.x, H11, a);
                    gv.x = *(uint32_t*)&a;
                    a = __hmul2(*(__half2*)&v0.y, H00);
                    a = __hfma2(*(__half2*)&v1.y, H01, a);
                    a = __hfma2(*(__half2*)&v2.y, H10, a);
                    a = __hfma2(*(__half2*)&v3.y, H11, a);
                    gv.y = *(uint32_t*)&a;
                    a = __hmul2(*(__half2*)&v0.z, H00);
                    a = __hfma2(*(__half2*)&v1.z, H01, a);
                    a = __hfma2(*(__half2*)&v2.z, H10, a);
                    a = __hfma2(*(__half2*)&v3.z, H11, a);
                    gv.z = *(uint32_t*)&a;
                    a = __hmul2(*(__half2*)&v0.w, H00);
                    a = __hfma2(*(__half2*)&v1.w, H01, a);
                    a = __hfma2(*(__half2*)&v2.w, H10, a);
                    a = __hfma2(*(__half2*)&v3.w, H11, a);
                    gv.w = *(uint32_t*)&a;
                }
                *(uint4*)(Ab + p * A_STRIDE + lc8 * 16) = gv;
            }
        }

        // ---- coords for tap k+1 ----
        if (k < 8) coords(k + 1, bf ^ 1);

        // ---- cp.async B(k+1) into ring slot (rb+1)%3 ----
        if (k < 8) {
            int nb = rb + 1; if (nb == 3) nb = 0;
            const char* src = (const char*)(g_wfragB + (size_t)(k + 1) * 1024);
            cp16(smB_u + (uint32_t)nb * 8192 + t * 16, src + t * 16);
        }
        asm volatile("cp.async.commit_group;" ::: "memory");
        asm volatile("cp.async.wait_group 1;" ::: "memory");   // B(k) complete
        __syncthreads();   // A[bf] ready; everyone past MMA(k-1)

        // ---- tensor phase: 4 ldmatrix.x4 (A) + B LDS + 16 HMMA ----
        {
            const uint32_t abase = smA_u + (uint32_t)(bf ? SM_A1 : SM_A0) +
                                   (uint32_t)m0 * A_STRIDE + ldsm_lane_off;
            uint32_t a[4][4];
#pragma unroll
            for (int q = 0; q < 4; q++) ldsm_x4(a[q], abase + q * 32);
            const uint2* bp = (const uint2*)(smc + SM_B0 + rb * 8192) + lane;
#pragma unroll
            for (int jj = 0; jj < 4; jj++) {
                int j = jbase + jj;
                uint2 bfr[4];
#pragma unroll
                for (int q = 0; q < 4; q++) bfr[q] = bp[(j * 4 + q) * 32];
#pragma unroll
                for (int q = 0; q < 4; q++) mma16816(acc[jj], a[q], bfr[q]);
            }
        }
        rb = rb + 1; if (rb == 3) rb = 0;
    }

    // ===================== epilogue: smem-staged coalesced store =====================
    __syncthreads();
    {
        float* sout = (float*)smc;   // [64][132] floats = 33792 B (overlaps A)
        int pxa = m0 + (lane >> 2);
#pragma unroll
        for (int jj = 0; jj < 4; jj++) {
            int o = (jbase + jj) * 8 + (lane & 3) * 2;
            sout[o * 132 + pxa]           = acc[jj][0];
            sout[(o + 1) * 132 + pxa]     = acc[jj][1];
            sout[o * 132 + pxa + 8]       = acc[jj][2];
            sout[(o + 1) * 132 + pxa + 8] = acc[jj][3];
        }
        __syncthreads();
#pragma unroll
        for (int it = 0; it < 4; it++) {
            int idx = it * 512 + t;
            int o = idx >> 5, pxq = idx & 31;
            float4 vv = *(const float4*)(sout + o * 132 + pxq * 4);
            *(float4*)(out + ((size_t)(b * CC + o) * HH + h) * WW + pxq * 4) = vv;
        }
    }
}

// ---------------------------------------------------------------------------
extern "C" void kernel_launch(void* const* d_in, const int* in_sizes, int n_in,
                              void* d_out, int out_size) {
    const float* x     = (const float*)d_in[0];
    const float* wmain = (const float*)d_in[1];
    const float* wrot  = (const float*)d_in[2];
    const float* brot  = (const float*)d_in[3];
    const float* wstr  = (const float*)d_in[4];
    const float* bstr  = (const float*)d_in[5];
    const float* wwhl  = (const float*)d_in[6];
    const float* bwhl  = (const float*)d_in[7];
    float* out = (float*)d_out;

    cudaFuncSetAttribute(k_main, cudaFuncAttributeMaxDynamicSharedMemorySize, SMEM_REQ);

    k_wprep<<<144, 256>>>(wmain, wrot, wstr, wwhl);
    k_transpose<<<dim3(512, 2, 8), dim3(32, 8)>>>(x);
    k_coef<<<BB * HH, 256>>>(x, brot, bstr, bwhl);
    k_main<<<BB * HH, 512, SMEM_REQ>>>(out);
}

// round 9
// speedup vs baseline: 1.5331x; 1.0342x over previous
#include <cuda_runtime.h>
#include <cuda_fp16.h>
#include <math.h>
#include <stdint.h>

#define BB 8
#define HH 128
#define WW 128
#define CC 64

// ---------------- scratch (allocation-free rule) ----------------
__device__ __align__(16) __half g_xh[BB*HH*WW*CC];      // NHWC x fp16 (gather)
__device__ __align__(16) uint2  g_wfragB[9*8*4*32];     // mma B-fragments fp16
__device__ __align__(16) float  g_wcoef[9*CC*4];        // [tap][c][{sin,cos,str,whl}]
__device__ __align__(16) float4 g_coef[BB*HH*WW];       // (sin, cos, wr*r, wr)

// ---------------- smem layout of k_main (dynamic, bytes) ----------------
#define A_STRIDE 144
#define SM_A0   0
#define SM_A1   18432
#define SM_B0   36864          // [3][8192] triple-buffered B ring
#define SM_SSB  61440          // int4[2][128]
#define SM_SSW  65536          // uint2[2][128]
#define SMEM_REQ 67584

// ---------------- helpers ----------------
__device__ __forceinline__ uint32_t smem_u32(const void* p) {
    uint32_t a;
    asm("{ .reg .u64 t; cvta.to.shared.u64 t, %1; cvt.u32.u64 %0, t; }" : "=r"(a) : "l"(p));
    return a;
}
__device__ __forceinline__ void ldsm_x4(uint32_t* r, uint32_t addr) {
    asm volatile("ldmatrix.sync.aligned.m8n8.x4.shared.b16 {%0,%1,%2,%3}, [%4];"
                 : "=r"(r[0]), "=r"(r[1]), "=r"(r[2]), "=r"(r[3]) : "r"(addr));
}
__device__ __forceinline__ void mma16816(float* d, const uint32_t* a, uint2 b) {
    asm volatile(
        "mma.sync.aligned.m16n8k16.row.col.f32.f16.f16.f32 "
        "{%0,%1,%2,%3}, {%4,%5,%6,%7}, {%8,%9}, {%0,%1,%2,%3};"
        : "+f"(d[0]), "+f"(d[1]), "+f"(d[2]), "+f"(d[3])
        : "r"(a[0]), "r"(a[1]), "r"(a[2]), "r"(a[3]), "r"(b.x), "r"(b.y));
}
__device__ __forceinline__ void cp16(uint32_t smem_dst, const void* gsrc) {
    asm volatile("cp.async.ca.shared.global [%0], [%1], 16;"
                 :: "r"(smem_dst), "l"(gsrc) : "memory");
}

// ---------------------------------------------------------------------------
// K0: weight prep — fp16 B-fragments for mma + coef weights
// ---------------------------------------------------------------------------
__global__ void k_wprep(const float* __restrict__ wmain,
                        const float* __restrict__ wrot,
                        const float* __restrict__ wstr,
                        const float* __restrict__ wwhl) {
    int idx = blockIdx.x * 256 + threadIdx.x;
    if (idx < 9 * CC * CC) {
        int o = idx % CC;
        int c = (idx / CC) % CC;
        int k = idx / (CC * CC);
        float w = wmain[(o * CC + c) * 9 + k];
        int j = o >> 3, lane_n = o & 7;
        int q = c >> 4, kk = c & 15;
        int reg = kk >> 3, r = kk & 7;
        int lane = lane_n * 4 + (r >> 1);
        int halfsel = r & 1;
        __half* dst = (__half*)g_wfragB;
        dst[(((size_t)(k * 8 + j) * 4 + q) * 32 + lane) * 4 + reg * 2 + halfsel] = __float2half(w);
    }
    if (idx < 9 * CC * 4) {
        int o   = idx & 3;
        int c   = (idx >> 2) % CC;
        int pos = idx / (CC * 4);
        float v;
        if (o == 0)      v = wrot[(0 * CC + c) * 9 + pos];
        else if (o == 1) v = wrot[(1 * CC + c) * 9 + pos];
        else if (o == 2) v = wstr[c * 9 + pos];
        else             v = wwhl[c * 9 + pos];
        g_wcoef[idx] = v;
    }
}

// ---------------------------------------------------------------------------
// K1: fused coefficient convs (fp32, NCHW x) + fp16 NHWC row transpose
// CTA = one (b,h) row; 256 threads: t&127 = pixel, t>>7 = channel half.
// Produces g_coef[bh] and g_xh row bh.
// ---------------------------------------------------------------------------
#define SXH_STRIDE 72   // halves; 144 B row stride (16B-aligned rows!)

__global__ void __launch_bounds__(256) k_xform(const float* __restrict__ x,
                                               const float* __restrict__ brot,
                                               const float* __restrict__ bstr,
                                               const float* __restrict__ bwhl) {
    __shared__ float4 swc[CC * 9];                    // [c][tap]
    __shared__ float4 red[256];
    __shared__ __align__(16) __half sxh[128 * SXH_STRIDE];

    const int t  = threadIdx.x;
    const int p  = t & 127;
    const int hf = t >> 7;
    const int bh = blockIdx.x;
    const int b  = bh >> 7;
    const int h  = bh & 127;

    {
        const float4* gw4 = (const float4*)g_wcoef;
        for (int i = t; i < CC * 9; i += 256) {
            int c = i / 9, tap = i - c * 9;
            swc[i] = gw4[tap * 64 + c];
        }
    }
    __syncthreads();

    float a0 = 0.f, a1 = 0.f, a2 = 0.f, a3 = 0.f;
    const int c0 = hf * 32;
    const float* xb = x + ((size_t)b * CC + c0) * (HH * WW);
#pragma unroll 4
    for (int ci = 0; ci < 32; ci++) {
        const float* xc = xb + (size_t)ci * (HH * WW);
        const float4* wc = swc + (c0 + ci) * 9;
#pragma unroll
        for (int dy = 0; dy < 3; dy++) {
            int y = h + dy - 1;
            if ((unsigned)y >= HH) continue;
            const float* row = xc + y * WW;
            float xm = (p > 0)       ? row[p - 1] : 0.f;
            float x0 = row[p];
            float xp = (p < WW - 1)  ? row[p + 1] : 0.f;
            if (dy == 1) sxh[p * SXH_STRIDE + c0 + ci] = __float2half(x0);
            float4 wA = wc[dy * 3 + 0];
            float4 wB = wc[dy * 3 + 1];
            float4 wC = wc[dy * 3 + 2];
            a0 += xm * wA.x + x0 * wB.x + xp * wC.x;
            a1 += xm * wA.y + x0 * wB.y + xp * wC.y;
            a2 += xm * wA.z + x0 * wB.z + xp * wC.z;
            a3 += xm * wA.w + x0 * wB.w + xp * wC.w;
        }
    }
    red[t] = make_float4(a0, a1, a2, a3);
    __syncthreads();   // red + sxh complete

    if (t < 128) {
        float4 u = red[t], v = red[t + 128];
        float s = u.x + v.x + brot[0];
        float c = u.y + v.y + brot[1];
        float n = sqrtf(s * s + c * c + 1e-6f);
        s /= n; c /= n;
        float r  = tanhf(u.z + v.z + bstr[0]) * 1.25f + 1.75f;
        float wl = tanhf(u.w + v.w + bwhl[0]) * 1.0f + 2.0f;
        g_coef[bh * WW + t] = make_float4(s, c, wl * r, wl);
    }

    // coalesced write of the fp16 NHWC row: 16 KB per CTA
    // rows are 144 B in smem (16B-aligned), 128 B in global
    {
        char* gdst = (char*)(g_xh + (size_t)bh * WW * CC);
        const char* ssrc = (const char*)sxh;
#pragma unroll
        for (int it = 0; it < 4; it++) {
            int idx = it * 256 + t;
            int px = idx >> 3, c8 = idx & 7;
            uint4 v = *(const uint4*)(ssrc + px * (SXH_STRIDE * 2) + c8 * 16);
            *(uint4*)(gdst + px * 128 + c8 * 16) = v;
        }
    }
}

// ---------------------------------------------------------------------------
// K2: deform gather (fp16) + mma.sync GEMM
// CTA = one (b,h) row (128 px), 512 threads / 16 warps, 2 CTAs/SM.
// Warp w: M-tile (w&7)*16, N-half (w>>3)*32 -> acc = 16 regs/thread.
// ---------------------------------------------------------------------------
__global__ void __launch_bounds__(512, 2) k_main(float* __restrict__ out) {
    extern __shared__ __align__(16) char smc[];
    int4*  ssb = (int4*)(smc + SM_SSB);    // [2][128]
    uint2* ssw = (uint2*)(smc + SM_SSW);   // [2][128]

    const int t    = threadIdx.x;
    const int wid  = t >> 5;
    const int lane = t & 31;
    const int bh   = blockIdx.x;
    const int b    = bh >> 7;
    const int h    = bh & 127;
    const char* xhimg = (const char*)(g_xh + (size_t)b * HH * WW * CC);

    float4 cf;
    if (t < 128) cf = g_coef[bh * WW + t];

    auto coords = [&](int k, int bf) {
        if (t >= 128) return;
        int kd3 = (k * 11) >> 5;
        float ky = (float)(kd3 - 1);
        float kx = (float)(k - 3 * kd3 - 1);
        float o0 = ky * cf.z;
        float o1 = kx * cf.w;
        float py = (float)h + cf.y * o0 + cf.x * o1;
        float px = (float)t - cf.x * o0 + cf.y * o1;
        float yf = floorf(py), xf = floorf(px);
        float ly = py - yf, lx = px - xf;
        int y0 = (int)yf, x0 = (int)xf;
        int y1 = y0 + 1,  x1 = x0 + 1;
        float w00 = (1.f - ly) * (1.f - lx);
        float w01 = (1.f - ly) * lx;
        float w10 = ly * (1.f - lx);
        float w11 = ly * lx;
        float vy0 = (y0 >= 0 && y0 < HH) ? 1.f : 0.f;
        float vy1 = (y1 >= 0 && y1 < HH) ? 1.f : 0.f;
        float vx0 = (x0 >= 0 && x0 < WW) ? 1.f : 0.f;
        float vx1 = (x1 >= 0 && x1 < WW) ? 1.f : 0.f;
        w00 *= vy0 * vx0; w01 *= vy0 * vx1;
        w10 *= vy1 * vx0; w11 *= vy1 * vx1;
        int yc0 = min(max(y0, 0), HH - 1);
        int yc1 = min(max(y1, 0), HH - 1);
        int xc0 = min(max(x0, 0), WW - 1);
        int xc1 = min(max(x1, 0), WW - 1);
        int4 bs;   // BYTE offsets into fp16 image (row = 128 B)
        bs.x = (yc0 * WW + xc0) << 7;
        bs.y = (yc0 * WW + xc1) << 7;
        bs.z = (yc1 * WW + xc0) << 7;
        bs.w = (yc1 * WW + xc1) << 7;
        ssb[bf * 128 + t] = bs;
        uint32_t wlo, whi;
        asm("cvt.rn.f16x2.f32 %0, %1, %2;" : "=r"(wlo) : "f"(w01), "f"(w00));
        asm("cvt.rn.f16x2.f32 %0, %1, %2;" : "=r"(whi) : "f"(w11), "f"(w10));
        ssw[bf * 128 + t] = make_uint2(wlo, whi);
    };

    const uint32_t smB_u = smem_u32(smc + SM_B0);

    // prime: cp.async B(0) -> ring buf 0 (8 KB = 512 x 16 B)
    {
        const char* src = (const char*)g_wfragB;
        cp16(smB_u + t * 16, src + t * 16);
        asm volatile("cp.async.commit_group;" ::: "memory");
    }
    coords(0, 0);
    __syncthreads();   // ssb0/ssw0 ready

    const uint32_t smA_u = smem_u32(smc);
    const int m0    = (wid & 7) * 16;
    const int jbase = (wid >> 3) * 4;
    const uint32_t ldsm_lane_off = (uint32_t)((lane & 15)) * A_STRIDE + ((lane >> 4) << 4);

    float acc[4][4];
#pragma unroll
    for (int j = 0; j < 4; j++)
#pragma unroll
        for (int i = 0; i < 4; i++) acc[j][i] = 0.f;

    const int lc8  = t & 7;    // channel octet (16 B fp16)
    const int gg64 = t >> 3;   // 0..63
    int rb = 0;                // ring slot of B(k)

#pragma unroll 1
    for (int k = 0; k < 9; k++) {
        const int bf = k & 1;

        // ---- gather tap k (fp16) into A[bf]: 2 pixels/thread ----
        {
            const int4*  sbp = ssb + bf * 128;
            const uint2* swp = ssw + bf * 128;
            char* Ab = smc + (bf ? SM_A1 : SM_A0);
#pragma unroll
            for (int it = 0; it < 2; it++) {
                int p = it * 64 + gg64;
                int4  bs = sbp[p];
                uint2 wv = swp[p];
                uint32_t u00 = __byte_perm(wv.x, 0, 0x1010);
                uint32_t u01 = __byte_perm(wv.x, 0, 0x3232);
                uint32_t u10 = __byte_perm(wv.y, 0, 0x1010);
                uint32_t u11 = __byte_perm(wv.y, 0, 0x3232);
                __half2 H00 = *(__half2*)&u00, H01 = *(__half2*)&u01;
                __half2 H10 = *(__half2*)&u10, H11 = *(__half2*)&u11;
                uint4 v0 = *(const uint4*)(xhimg + bs.x + lc8 * 16);
                uint4 v1 = *(const uint4*)(xhimg + bs.y + lc8 * 16);
                uint4 v2 = *(const uint4*)(xhimg + bs.z + lc8 * 16);
                uint4 v3 = *(const uint4*)(xhimg + bs.w + lc8 * 16);
                uint4 gv;
                {
                    __half2 a;
                    a = __hmul2(*(__half2*)&v0.x, H00);
                    a = __hfma2(*(__half2*)&v1.x, H01, a);
                    a = __hfma2(*(__half2*)&v2.x, H10, a);
                    a = __hfma2(*(__half2*)&v3.x, H11, a);
                    gv.x = *(uint32_t*)&a;
                    a = __hmul2(*(__half2*)&v0.y, H00);
                    a = __hfma2(*(__half2*)&v1.y, H01, a);
                    a = __hfma2(*(__half2*)&v2.y, H10, a);
                    a = __hfma2(*(__half2*)&v3.y, H11, a);
                    gv.y = *(uint32_t*)&a;
                    a = __hmul2(*(__half2*)&v0.z, H00);
                    a = __hfma2(*(__half2*)&v1.z, H01, a);
                    a = __hfma2(*(__half2*)&v2.z, H10, a);
                    a = __hfma2(*(__half2*)&v3.z, H11, a);
                    gv.z = *(uint32_t*)&a;
                    a = __hmul2(*(__half2*)&v0.w, H00);
                    a = __hfma2(*(__half2*)&v1.w, H01, a);
                    a = __hfma2(*(__half2*)&v2.w, H10, a);
                    a = __hfma2(*(__half2*)&v3.w, H11, a);
                    gv.w = *(uint32_t*)&a;
                }
                *(uint4*)(Ab + p * A_STRIDE + lc8 * 16) = gv;
            }
        }

        // ---- coords for tap k+1 ----
        if (k < 8) coords(k + 1, bf ^ 1);

        // ---- cp.async B(k+1) into ring slot (rb+1)%3 ----
        if (k < 8) {
            int nb = rb + 1; if (nb == 3) nb = 0;
            const char* src = (const char*)(g_wfragB + (size_t)(k + 1) * 1024);
            cp16(smB_u + (uint32_t)nb * 8192 + t * 16, src + t * 16);
        }
        asm volatile("cp.async.commit_group;" ::: "memory");
        asm volatile("cp.async.wait_group 1;" ::: "memory");   // B(k) complete
        __syncthreads();   // A[bf] ready; everyone past MMA(k-1)

        // ---- tensor phase: 4 ldmatrix.x4 (A) + B LDS + 16 HMMA ----
        {
            const uint32_t abase = smA_u + (uint32_t)(bf ? SM_A1 : SM_A0) +
                                   (uint32_t)m0 * A_STRIDE + ldsm_lane_off;
            uint32_t a[4][4];
#pragma unroll
            for (int q = 0; q < 4; q++) ldsm_x4(a[q], abase + q * 32);
            const uint2* bp = (const uint2*)(smc + SM_B0 + rb * 8192) + lane;
#pragma unroll
            for (int jj = 0; jj < 4; jj++) {
                int j = jbase + jj;
                uint2 bfr[4];
#pragma unroll
                for (int q = 0; q < 4; q++) bfr[q] = bp[(j * 4 + q) * 32];
#pragma unroll
                for (int q = 0; q < 4; q++) mma16816(acc[jj], a[q], bfr[q]);
            }
        }
        rb = rb + 1; if (rb == 3) rb = 0;
    }

    // ===================== epilogue: smem-staged coalesced store =====================
    __syncthreads();
    {
        float* sout = (float*)smc;   // [64][132] floats = 33792 B (overlaps A)
        int pxa = m0 + (lane >> 2);
#pragma unroll
        for (int jj = 0; jj < 4; jj++) {
            int o = (jbase + jj) * 8 + (lane & 3) * 2;
            sout[o * 132 + pxa]           = acc[jj][0];
            sout[(o + 1) * 132 + pxa]     = acc[jj][1];
            sout[o * 132 + pxa + 8]       = acc[jj][2];
            sout[(o + 1) * 132 + pxa + 8] = acc[jj][3];
        }
        __syncthreads();
#pragma unroll
        for (int it = 0; it < 4; it++) {
            int idx = it * 512 + t;
            int o = idx >> 5, pxq = idx & 31;
            float4 vv = *(const float4*)(sout + o * 132 + pxq * 4);
            *(float4*)(out + ((size_t)(b * CC + o) * HH + h) * WW + pxq * 4) = vv;
        }
    }
}

// ---------------------------------------------------------------------------
extern "C" void kernel_launch(void* const* d_in, const int* in_sizes, int n_in,
                              void* d_out, int out_size) {
    const float* x     = (const float*)d_in[0];
    const float* wmain = (const float*)d_in[1];
    const float* wrot  = (const float*)d_in[2];
    const float* brot  = (const float*)d_in[3];
    const float* wstr  = (const float*)d_in[4];
    const float* bstr  = (const float*)d_in[5];
    const float* wwhl  = (const float*)d_in[6];
    const float* bwhl  = (const float*)d_in[7];
    float* out = (float*)d_out;

    cudaFuncSetAttribute(k_main, cudaFuncAttributeMaxDynamicSharedMemorySize, SMEM_REQ);

    k_wprep<<<144, 256>>>(wmain, wrot, wstr, wwhl);
    k_xform<<<BB * HH, 256>>>(x, brot, bstr, bwhl);
    k_main<<<BB * HH, 512, SMEM_REQ>>>(out);
}

// round 10
// speedup vs baseline: 1.5400x; 1.0045x over previous
#include <cuda_runtime.h>
#include <cuda_fp16.h>
#include <math.h>
#include <stdint.h>

#define BB 8
#define HH 128
#define WW 128
#define CC 64

// ---------------- scratch (allocation-free rule) ----------------
__device__ __align__(16) __half g_xh[BB*HH*WW*CC];      // NHWC x fp16 (gather)
__device__ __align__(16) uint2  g_wfragB[9*8*4*32];     // mma B-fragments fp16
__device__ __align__(16) float  g_wcoef[9*CC*4];        // [tap][c][{sin,cos,str,whl}]
__device__ __align__(16) float4 g_coef[BB*HH*WW];       // (sin, cos, wr*r, wr)

// ---------------- smem layout of k_main (dynamic, bytes) ----------------
#define A_STRIDE 144
#define SM_A0   0
#define SM_A1   18432
#define SM_B0   36864          // [3][8192] triple-buffered B ring
#define SM_SSB  61440          // int4[2][128]
#define SM_SSW  65536          // uint2[2][128]
#define SMEM_REQ 67584

// ---------------- helpers ----------------
__device__ __forceinline__ uint32_t smem_u32(const void* p) {
    uint32_t a;
    asm("{ .reg .u64 t; cvta.to.shared.u64 t, %1; cvt.u32.u64 %0, t; }" : "=r"(a) : "l"(p));
    return a;
}
__device__ __forceinline__ void ldsm_x4(uint32_t* r, uint32_t addr) {
    asm volatile("ldmatrix.sync.aligned.m8n8.x4.shared.b16 {%0,%1,%2,%3}, [%4];"
                 : "=r"(r[0]), "=r"(r[1]), "=r"(r[2]), "=r"(r[3]) : "r"(addr));
}
__device__ __forceinline__ void mma16816(float* d, const uint32_t* a, uint2 b) {
    asm volatile(
        "mma.sync.aligned.m16n8k16.row.col.f32.f16.f16.f32 "
        "{%0,%1,%2,%3}, {%4,%5,%6,%7}, {%8,%9}, {%0,%1,%2,%3};"
        : "+f"(d[0]), "+f"(d[1]), "+f"(d[2]), "+f"(d[3])
        : "r"(a[0]), "r"(a[1]), "r"(a[2]), "r"(a[3]), "r"(b.x), "r"(b.y));
}
__device__ __forceinline__ void cp16(uint32_t smem_dst, const void* gsrc) {
    asm volatile("cp.async.ca.shared.global [%0], [%1], 16;"
                 :: "r"(smem_dst), "l"(gsrc) : "memory");
}
// packed fp32x2 FMA (Blackwell): d = a * b + d, componentwise
__device__ __forceinline__ void ffma2(uint64_t& d, uint64_t a, uint64_t b) {
    asm("fma.rn.f32x2 %0, %1, %2, %0;" : "+l"(d) : "l"(a), "l"(b));
}
__device__ __forceinline__ uint64_t bcast2(float v) {
    uint64_t r;
    asm("mov.b64 %0, {%1, %1};" : "=l"(r) : "f"(v));
    return r;
}

// ---------------------------------------------------------------------------
// K0: weight prep — fp16 B-fragments for mma + coef weights
// wmain read COALESCED (idx = memory order), writes scattered (cheap)
// ---------------------------------------------------------------------------
__global__ void k_wprep(const float* __restrict__ wmain,
                        const float* __restrict__ wrot,
                        const float* __restrict__ wstr,
                        const float* __restrict__ wwhl) {
    int idx = blockIdx.x * 256 + threadIdx.x;
    if (idx < 9 * CC * CC) {
        int k = idx % 9;
        int c = (idx / 9) % CC;
        int o = idx / (9 * CC);
        float w = wmain[idx];
        int j = o >> 3, lane_n = o & 7;
        int q = c >> 4, kk = c & 15;
        int reg = kk >> 3, r = kk & 7;
        int lane = lane_n * 4 + (r >> 1);
        int halfsel = r & 1;
        __half* dst = (__half*)g_wfragB;
        dst[(((size_t)(k * 8 + j) * 4 + q) * 32 + lane) * 4 + reg * 2 + halfsel] = __float2half(w);
    }
    if (idx < 9 * CC * 4) {
        int o   = idx & 3;
        int c   = (idx >> 2) % CC;
        int pos = idx / (CC * 4);
        float v;
        if (o == 0)      v = wrot[(0 * CC + c) * 9 + pos];
        else if (o == 1) v = wrot[(1 * CC + c) * 9 + pos];
        else if (o == 2) v = wstr[c * 9 + pos];
        else             v = wwhl[c * 9 + pos];
        g_wcoef[idx] = v;
    }
}

// ---------------------------------------------------------------------------
// K1: fused coefficient convs (fp32 FFMA2, NCHW x) + fp16 NHWC row transpose
// CTA = one (b,h) row; 256 threads: t&127 = pixel, t>>7 = channel half.
// ---------------------------------------------------------------------------
#define SXH_STRIDE 72   // halves; 144 B row stride (16B-aligned rows)

__global__ void __launch_bounds__(256) k_xform(const float* __restrict__ x,
                                               const float* __restrict__ brot,
                                               const float* __restrict__ bstr,
                                               const float* __restrict__ bwhl) {
    __shared__ float4 swc[CC * 9];                    // [c][tap]
    __shared__ float4 red[256];
    __shared__ __align__(16) __half sxh[128 * SXH_STRIDE];

    const int t  = threadIdx.x;
    const int p  = t & 127;
    const int hf = t >> 7;
    const int bh = blockIdx.x;
    const int b  = bh >> 7;
    const int h  = bh & 127;

    {
        const float4* gw4 = (const float4*)g_wcoef;
        for (int i = t; i < CC * 9; i += 256) {
            int c = i / 9, tap = i - c * 9;
            swc[i] = gw4[tap * 64 + c];
        }
    }
    __syncthreads();

    uint64_t acc01 = 0ull, acc23 = 0ull;   // packed (a0,a1), (a2,a3)
    const int c0 = hf * 32;
    const float* xb = x + ((size_t)b * CC + c0) * (HH * WW);
#pragma unroll 4
    for (int ci = 0; ci < 32; ci++) {
        const float* xc = xb + (size_t)ci * (HH * WW);
        const ulonglong2* wc = (const ulonglong2*)(swc + (c0 + ci) * 9);
#pragma unroll
        for (int dy = 0; dy < 3; dy++) {
            int y = h + dy - 1;
            if ((unsigned)y >= HH) continue;
            const float* row = xc + y * WW;
            float xmf = (p > 0)      ? row[p - 1] : 0.f;
            float x0f = row[p];
            float xpf = (p < WW - 1) ? row[p + 1] : 0.f;
            if (dy == 1) sxh[p * SXH_STRIDE + c0 + ci] = __float2half(x0f);
            uint64_t xm = bcast2(xmf), x0 = bcast2(x0f), xp = bcast2(xpf);
            ulonglong2 wA = wc[dy * 3 + 0];
            ulonglong2 wB = wc[dy * 3 + 1];
            ulonglong2 wC = wc[dy * 3 + 2];
            ffma2(acc01, xm, wA.x); ffma2(acc23, xm, wA.y);
            ffma2(acc01, x0, wB.x); ffma2(acc23, x0, wB.y);
            ffma2(acc01, xp, wC.x); ffma2(acc23, xp, wC.y);
        }
    }
    {
        float a0, a1, a2, a3;
        asm("mov.b64 {%0, %1}, %2;" : "=f"(a0), "=f"(a1) : "l"(acc01));
        asm("mov.b64 {%0, %1}, %2;" : "=f"(a2), "=f"(a3) : "l"(acc23));
        red[t] = make_float4(a0, a1, a2, a3);
    }
    __syncthreads();   // red + sxh complete

    if (t < 128) {
        float4 u = red[t], v = red[t + 128];
        float s = u.x + v.x + brot[0];
        float c = u.y + v.y + brot[1];
        float n = sqrtf(s * s + c * c + 1e-6f);
        s /= n; c /= n;
        float r  = tanhf(u.z + v.z + bstr[0]) * 1.25f + 1.75f;
        float wl = tanhf(u.w + v.w + bwhl[0]) * 1.0f + 2.0f;
        g_coef[bh * WW + t] = make_float4(s, c, wl * r, wl);
    }

    // coalesced write of the fp16 NHWC row: 16 KB per CTA
    {
        char* gdst = (char*)(g_xh + (size_t)bh * WW * CC);
        const char* ssrc = (const char*)sxh;
#pragma unroll
        for (int it = 0; it < 4; it++) {
            int idx = it * 256 + t;
            int px = idx >> 3, c8 = idx & 7;
            uint4 v = *(const uint4*)(ssrc + px * (SXH_STRIDE * 2) + c8 * 16);
            *(uint4*)(gdst + px * 128 + c8 * 16) = v;
        }
    }
}

// ---------------------------------------------------------------------------
// K2: deform gather (fp16) + mma.sync GEMM
// CTA = one (b,h) row (128 px), 512 threads / 16 warps, 2 CTAs/SM.
// Warp w: M-tile (w&7)*16, N-half (w>>3)*32 -> acc = 16 regs/thread.
// ---------------------------------------------------------------------------
__global__ void __launch_bounds__(512, 2) k_main(float* __restrict__ out) {
    extern __shared__ __align__(16) char smc[];
    int4*  ssb = (int4*)(smc + SM_SSB);    // [2][128]
    uint2* ssw = (uint2*)(smc + SM_SSW);   // [2][128]

    const int t    = threadIdx.x;
    const int wid  = t >> 5;
    const int lane = t & 31;
    const int bh   = blockIdx.x;
    const int b    = bh >> 7;
    const int h    = bh & 127;
    const char* xhimg = (const char*)(g_xh + (size_t)b * HH * WW * CC);

    float4 cf;
    if (t < 128) cf = g_coef[bh * WW + t];

    auto coords = [&](int k, int bf) {
        if (t >= 128) return;
        int kd3 = (k * 11) >> 5;
        float ky = (float)(kd3 - 1);
        float kx = (float)(k - 3 * kd3 - 1);
        float o0 = ky * cf.z;
        float o1 = kx * cf.w;
        float py = (float)h + cf.y * o0 + cf.x * o1;
        float px = (float)t - cf.x * o0 + cf.y * o1;
        float yf = floorf(py), xf = floorf(px);
        float ly = py - yf, lx = px - xf;
        int y0 = (int)yf, x0 = (int)xf;
        int y1 = y0 + 1,  x1 = x0 + 1;
        float w00 = (1.f - ly) * (1.f - lx);
        float w01 = (1.f - ly) * lx;
        float w10 = ly * (1.f - lx);
        float w11 = ly * lx;
        float vy0 = (y0 >= 0 && y0 < HH) ? 1.f : 0.f;
        float vy1 = (y1 >= 0 && y1 < HH) ? 1.f : 0.f;
        float vx0 = (x0 >= 0 && x0 < WW) ? 1.f : 0.f;
        float vx1 = (x1 >= 0 && x1 < WW) ? 1.f : 0.f;
        w00 *= vy0 * vx0; w01 *= vy0 * vx1;
        w10 *= vy1 * vx0; w11 *= vy1 * vx1;
        int yc0 = min(max(y0, 0), HH - 1);
        int yc1 = min(max(y1, 0), HH - 1);
        int xc0 = min(max(x0, 0), WW - 1);
        int xc1 = min(max(x1, 0), WW - 1);
        int4 bs;   // BYTE offsets into fp16 image (row = 128 B)
        bs.x = (yc0 * WW + xc0) << 7;
        bs.y = (yc0 * WW + xc1) << 7;
        bs.z = (yc1 * WW + xc0) << 7;
        bs.w = (yc1 * WW + xc1) << 7;
        ssb[bf * 128 + t] = bs;
        uint32_t wlo, whi;
        asm("cvt.rn.f16x2.f32 %0, %1, %2;" : "=r"(wlo) : "f"(w01), "f"(w00));
        asm("cvt.rn.f16x2.f32 %0, %1, %2;" : "=r"(whi) : "f"(w11), "f"(w10));
        ssw[bf * 128 + t] = make_uint2(wlo, whi);
    };

    const uint32_t smB_u = smem_u32(smc + SM_B0);

    // prime: cp.async B(0) -> ring buf 0 (8 KB = 512 x 16 B)
    {
        const char* src = (const char*)g_wfragB;
        cp16(smB_u + t * 16, src + t * 16);
        asm volatile("cp.async.commit_group;" ::: "memory");
    }
    coords(0, 0);
    __syncthreads();   // ssb0/ssw0 ready

    const uint32_t smA_u = smem_u32(smc);
    const int m0    = (wid & 7) * 16;
    const int jbase = (wid >> 3) * 4;
    const uint32_t ldsm_lane_off = (uint32_t)((lane & 15)) * A_STRIDE + ((lane >> 4) << 4);

    float acc[4][4];
#pragma unroll
    for (int j = 0; j < 4; j++)
#pragma unroll
        for (int i = 0; i < 4; i++) acc[j][i] = 0.f;

    const int lc8  = t & 7;    // channel octet (16 B fp16)
    const int gg64 = t >> 3;   // 0..63
    int rb = 0;                // ring slot of B(k)

#pragma unroll 1
    for (int k = 0; k < 9; k++) {
        const int bf = k & 1;

        // ---- gather tap k (fp16) into A[bf]: 2 pixels/thread ----
        {
            const int4*  sbp = ssb + bf * 128;
            const uint2* swp = ssw + bf * 128;
            char* Ab = smc + (bf ? SM_A1 : SM_A0);
#pragma unroll
            for (int it = 0; it < 2; it++) {
                int p = it * 64 + gg64;
                int4  bs = sbp[p];
                uint2 wv = swp[p];
                uint32_t u00 = __byte_perm(wv.x, 0, 0x1010);
                uint32_t u01 = __byte_perm(wv.x, 0, 0x3232);
                uint32_t u10 = __byte_perm(wv.y, 0, 0x1010);
                uint32_t u11 = __byte_perm(wv.y, 0, 0x3232);
                __half2 H00 = *(__half2*)&u00, H01 = *(__half2*)&u01;
                __half2 H10 = *(__half2*)&u10, H11 = *(__half2*)&u11;
                uint4 v0 = *(const uint4*)(xhimg + bs.x + lc8 * 16);
                uint4 v1 = *(const uint4*)(xhimg + bs.y + lc8 * 16);
                uint4 v2 = *(const uint4*)(xhimg + bs.z + lc8 * 16);
                uint4 v3 = *(const uint4*)(xhimg + bs.w + lc8 * 16);
                uint4 gv;
                {
                    __half2 a;
                    a = __hmul2(*(__half2*)&v0.x, H00);
                    a = __hfma2(*(__half2*)&v1.x, H01, a);
                    a = __hfma2(*(__half2*)&v2.x, H10, a);
                    a = __hfma2(*(__half2*)&v3.x, H11, a);
                    gv.x = *(uint32_t*)&a;
                    a = __hmul2(*(__half2*)&v0.y, H00);
                    a = __hfma2(*(__half2*)&v1.y, H01, a);
                    a = __hfma2(*(__half2*)&v2.y, H10, a);
                    a = __hfma2(*(__half2*)&v3.y, H11, a);
                    gv.y = *(uint32_t*)&a;
                    a = __hmul2(*(__half2*)&v0.z, H00);
                    a = __hfma2(*(__half2*)&v1.z, H01, a);
                    a = __hfma2(*(__half2*)&v2.z, H10, a);
                    a = __hfma2(*(__half2*)&v3.z, H11, a);
                    gv.z = *(uint32_t*)&a;
                    a = __hmul2(*(__half2*)&v0.w, H00);
                    a = __hfma2(*(__half2*)&v1.w, H01, a);
                    a = __hfma2(*(__half2*)&v2.w, H10, a);
                    a = __hfma2(*(__half2*)&v3.w, H11, a);
                    gv.w = *(uint32_t*)&a;
                }
                *(uint4*)(Ab + p * A_STRIDE + lc8 * 16) = gv;
            }
        }

        // ---- coords for tap k+1 ----
        if (k < 8) coords(k + 1, bf ^ 1);

        // ---- cp.async B(k+1) into ring slot (rb+1)%3 ----
        if (k < 8) {
            int nb = rb + 1; if (nb == 3) nb = 0;
            const char* src = (const char*)(g_wfragB + (size_t)(k + 1) * 1024);
            cp16(smB_u + (uint32_t)nb * 8192 + t * 16, src + t * 16);
        }
        asm volatile("cp.async.commit_group;" ::: "memory");
        asm volatile("cp.async.wait_group 1;" ::: "memory");   // B(k) complete
        __syncthreads();   // A[bf] ready; everyone past MMA(k-1)

        // ---- tensor phase: 4 ldmatrix.x4 (A) + B LDS + 16 HMMA ----
        {
            const uint32_t abase = smA_u + (uint32_t)(bf ? SM_A1 : SM_A0) +
                                   (uint32_t)m0 * A_STRIDE + ldsm_lane_off;
            uint32_t a[4][4];
#pragma unroll
            for (int q = 0; q < 4; q++) ldsm_x4(a[q], abase + q * 32);
            const uint2* bp = (const uint2*)(smc + SM_B0 + rb * 8192) + lane;
#pragma unroll
            for (int jj = 0; jj < 4; jj++) {
                int j = jbase + jj;
                uint2 bfr[4];
#pragma unroll
                for (int q = 0; q < 4; q++) bfr[q] = bp[(j * 4 + q) * 32];
#pragma unroll
                for (int q = 0; q < 4; q++) mma16816(acc[jj], a[q], bfr[q]);
            }
        }
        rb = rb + 1; if (rb == 3) rb = 0;
    }

    // ===================== epilogue: smem-staged coalesced store =====================
    __syncthreads();
    {
        float* sout = (float*)smc;   // [64][132] floats = 33792 B (overlaps A)
        int pxa = m0 + (lane >> 2);
#pragma unroll
        for (int jj = 0; jj < 4; jj++) {
            int o = (jbase + jj) * 8 + (lane & 3) * 2;
            sout[o * 132 + pxa]           = acc[jj][0];
            sout[(o + 1) * 132 + pxa]     = acc[jj][1];
            sout[o * 132 + pxa + 8]       = acc[jj][2];
            sout[(o + 1) * 132 + pxa + 8] = acc[jj][3];
        }
        __syncthreads();
#pragma unroll
        for (int it = 0; it < 4; it++) {
            int idx = it * 512 + t;
            int o = idx >> 5, pxq = idx & 31;
            float4 vv = *(const float4*)(sout + o * 132 + pxq * 4);
            *(float4*)(out + ((size_t)(b * CC + o) * HH + h) * WW + pxq * 4) = vv;
        }
    }
}

// ---------------------------------------------------------------------------
extern "C" void kernel_launch(void* const* d_in, const int* in_sizes, int n_in,
                              void* d_out, int out_size) {
    const float* x     = (const float*)d_in[0];
    const float* wmain = (const float*)d_in[1];
    const float* wrot  = (const float*)d_in[2];
    const float* brot  = (const float*)d_in[3];
    const float* wstr  = (const float*)d_in[4];
    const float* bstr  = (const float*)d_in[5];
    const float* wwhl  = (const float*)d_in[6];
    const float* bwhl  = (const float*)d_in[7];
    float* out = (float*)d_out;

    cudaFuncSetAttribute(k_main, cudaFuncAttributeMaxDynamicSharedMemorySize, SMEM_REQ);

    k_wprep<<<144, 256>>>(wmain, wrot, wstr, wwhl);
    k_xform<<<BB * HH, 256>>>(x, brot, bstr, bwhl);
    k_main<<<BB * HH, 512, SMEM_REQ>>>(out);
}

// round 11
// speedup vs baseline: 1.5694x; 1.0191x over previous
#include <cuda_runtime.h>
#include <cuda_fp16.h>
#include <math.h>
#include <stdint.h>

#define BB 8
#define HH 128
#define WW 128
#define CC 64

// ---------------- scratch (allocation-free rule) ----------------
__device__ __align__(16) __half g_xh[BB*HH*WW*CC];      // NHWC x fp16 (gather)
__device__ __align__(16) uint2  g_wfragB[9*8*4*32];     // mma B-fragments fp16
__device__ __align__(16) float4 g_coef[BB*HH*WW];       // (sin, cos, wr*r, wr)

// ---------------- smem layout of k_main (dynamic, bytes) ----------------
#define A_STRIDE 144
#define SM_A0   0
#define SM_A1   18432
#define SM_B0   36864          // [3][8192] triple-buffered B ring
#define SM_SSB  61440          // int4[2][128]
#define SM_SSW  65536          // uint2[2][128]
#define SMEM_REQ 67584

// ---------------- helpers ----------------
__device__ __forceinline__ uint32_t smem_u32(const void* p) {
    uint32_t a;
    asm("{ .reg .u64 t; cvta.to.shared.u64 t, %1; cvt.u32.u64 %0, t; }" : "=r"(a) : "l"(p));
    return a;
}
__device__ __forceinline__ void ldsm_x4(uint32_t* r, uint32_t addr) {
    asm volatile("ldmatrix.sync.aligned.m8n8.x4.shared.b16 {%0,%1,%2,%3}, [%4];"
                 : "=r"(r[0]), "=r"(r[1]), "=r"(r[2]), "=r"(r[3]) : "r"(addr));
}
__device__ __forceinline__ void mma16816(float* d, const uint32_t* a, uint2 b) {
    asm volatile(
        "mma.sync.aligned.m16n8k16.row.col.f32.f16.f16.f32 "
        "{%0,%1,%2,%3}, {%4,%5,%6,%7}, {%8,%9}, {%0,%1,%2,%3};"
        : "+f"(d[0]), "+f"(d[1]), "+f"(d[2]), "+f"(d[3])
        : "r"(a[0]), "r"(a[1]), "r"(a[2]), "r"(a[3]), "r"(b.x), "r"(b.y));
}
__device__ __forceinline__ void cp16(uint32_t smem_dst, const void* gsrc) {
    asm volatile("cp.async.ca.shared.global [%0], [%1], 16;"
                 :: "r"(smem_dst), "l"(gsrc) : "memory");
}
// packed fp32x2 FMA (Blackwell): d = a * b + d, componentwise
__device__ __forceinline__ void ffma2(uint64_t& d, uint64_t a, uint64_t b) {
    asm("fma.rn.f32x2 %0, %1, %2, %0;" : "+l"(d) : "l"(a), "l"(b));
}
__device__ __forceinline__ uint64_t bcast2(float v) {
    uint64_t r;
    asm("mov.b64 %0, {%1, %1};" : "=l"(r) : "f"(v));
    return r;
}

// ---------------------------------------------------------------------------
// K1: fused weight prep + coefficient convs (FFMA2) + fp16 NHWC transpose
// CTA = one (b,h) row; 256 threads: t&127 = pixel, t>>7 = channel half.
// Also: threads t<36 convert this CTA's 36-element slice of wmain into
// fp16 mma B-fragments (1024 CTAs x 36 = 36864 = 9*64*64 exactly).
// ---------------------------------------------------------------------------
#define SXH_STRIDE 72   // halves; 144 B row stride (16B-aligned rows)

__global__ void __launch_bounds__(256) k_xform(const float* __restrict__ x,
                                               const float* __restrict__ wmain,
                                               const float* __restrict__ wrot,
                                               const float* __restrict__ brot,
                                               const float* __restrict__ wstr,
                                               const float* __restrict__ bstr,
                                               const float* __restrict__ wwhl,
                                               const float* __restrict__ bwhl) {
    __shared__ float4 swc[CC * 9];                    // [c][tap]
    __shared__ float4 red[256];
    __shared__ __align__(16) __half sxh[128 * SXH_STRIDE];

    const int t  = threadIdx.x;
    const int p  = t & 127;
    const int hf = t >> 7;
    const int bh = blockIdx.x;
    const int b  = bh >> 7;
    const int h  = bh & 127;

    // ---- B-fragment prep slice (independent; done before any sync) ----
    if (t < 36) {
        int idx = bh * 36 + t;
        int k = idx % 9;
        int c = (idx / 9) % CC;
        int o = idx / (9 * CC);
        float w = wmain[idx];
        int j = o >> 3, lane_n = o & 7;
        int q = c >> 4, kk = c & 15;
        int reg = kk >> 3, r = kk & 7;
        int lane = lane_n * 4 + (r >> 1);
        int halfsel = r & 1;
        __half* dst = (__half*)g_wfragB;
        dst[(((size_t)(k * 8 + j) * 4 + q) * 32 + lane) * 4 + reg * 2 + halfsel] = __float2half(w);
    }

    // ---- coef weights straight from inputs: swc[c*9+tap] ----
    for (int i = t; i < CC * 9; i += 256) {
        int c = i / 9, tap = i - c * 9;
        swc[i] = make_float4(wrot[(0 * CC + c) * 9 + tap],
                             wrot[(1 * CC + c) * 9 + tap],
                             wstr[c * 9 + tap],
                             wwhl[c * 9 + tap]);
    }
    __syncthreads();

    uint64_t acc01 = 0ull, acc23 = 0ull;   // packed (a0,a1), (a2,a3)
    const int c0 = hf * 32;
    const float* xb = x + ((size_t)b * CC + c0) * (HH * WW);
#pragma unroll 4
    for (int ci = 0; ci < 32; ci++) {
        const float* xc = xb + (size_t)ci * (HH * WW);
        const ulonglong2* wc = (const ulonglong2*)(swc + (c0 + ci) * 9);
#pragma unroll
        for (int dy = 0; dy < 3; dy++) {
            int y = h + dy - 1;
            if ((unsigned)y >= HH) continue;
            const float* row = xc + y * WW;
            float xmf = (p > 0)      ? row[p - 1] : 0.f;
            float x0f = row[p];
            float xpf = (p < WW - 1) ? row[p + 1] : 0.f;
            if (dy == 1) sxh[p * SXH_STRIDE + c0 + ci] = __float2half(x0f);
            uint64_t xm = bcast2(xmf), x0 = bcast2(x0f), xp = bcast2(xpf);
            ulonglong2 wA = wc[dy * 3 + 0];
            ulonglong2 wB = wc[dy * 3 + 1];
            ulonglong2 wC = wc[dy * 3 + 2];
            ffma2(acc01, xm, wA.x); ffma2(acc23, xm, wA.y);
            ffma2(acc01, x0, wB.x); ffma2(acc23, x0, wB.y);
            ffma2(acc01, xp, wC.x); ffma2(acc23, xp, wC.y);
        }
    }
    {
        float a0, a1, a2, a3;
        asm("mov.b64 {%0, %1}, %2;" : "=f"(a0), "=f"(a1) : "l"(acc01));
        asm("mov.b64 {%0, %1}, %2;" : "=f"(a2), "=f"(a3) : "l"(acc23));
        red[t] = make_float4(a0, a1, a2, a3);
    }
    __syncthreads();   // red + sxh complete

    if (t < 128) {
        float4 u = red[t], v = red[t + 128];
        float s = u.x + v.x + brot[0];
        float c = u.y + v.y + brot[1];
        float n = sqrtf(s * s + c * c + 1e-6f);
        s /= n; c /= n;
        float r  = tanhf(u.z + v.z + bstr[0]) * 1.25f + 1.75f;
        float wl = tanhf(u.w + v.w + bwhl[0]) * 1.0f + 2.0f;
        g_coef[bh * WW + t] = make_float4(s, c, wl * r, wl);
    }

    // coalesced write of the fp16 NHWC row: 16 KB per CTA
    {
        char* gdst = (char*)(g_xh + (size_t)bh * WW * CC);
        const char* ssrc = (const char*)sxh;
#pragma unroll
        for (int it = 0; it < 4; it++) {
            int idx = it * 256 + t;
            int px = idx >> 3, c8 = idx & 7;
            uint4 v = *(const uint4*)(ssrc + px * (SXH_STRIDE * 2) + c8 * 16);
            *(uint4*)(gdst + px * 128 + c8 * 16) = v;
        }
    }
}

// ---------------------------------------------------------------------------
// K2: deform gather (fp16) + mma.sync GEMM
// CTA = one (b,h) row (128 px), 512 threads / 16 warps, 2 CTAs/SM.
// Warp w: M-tile (w&7)*16, N-half (w>>3)*32 -> acc = 16 regs/thread.
// ---------------------------------------------------------------------------
__global__ void __launch_bounds__(512, 2) k_main(float* __restrict__ out) {
    extern __shared__ __align__(16) char smc[];
    int4*  ssb = (int4*)(smc + SM_SSB);    // [2][128]
    uint2* ssw = (uint2*)(smc + SM_SSW);   // [2][128]

    const int t    = threadIdx.x;
    const int wid  = t >> 5;
    const int lane = t & 31;
    const int bh   = blockIdx.x;
    const int b    = bh >> 7;
    const int h    = bh & 127;
    const char* xhimg = (const char*)(g_xh + (size_t)b * HH * WW * CC);

    float4 cf;
    if (t < 128) cf = g_coef[bh * WW + t];

    auto coords = [&](int k, int bf) {
        if (t >= 128) return;
        int kd3 = (k * 11) >> 5;
        float ky = (float)(kd3 - 1);
        float kx = (float)(k - 3 * kd3 - 1);
        float o0 = ky * cf.z;
        float o1 = kx * cf.w;
        float py = (float)h + cf.y * o0 + cf.x * o1;
        float px = (float)t - cf.x * o0 + cf.y * o1;
        float yf = floorf(py), xf = floorf(px);
        float ly = py - yf, lx = px - xf;
        int y0 = (int)yf, x0 = (int)xf;
        int y1 = y0 + 1,  x1 = x0 + 1;
        float w00 = (1.f - ly) * (1.f - lx);
        float w01 = (1.f - ly) * lx;
        float w10 = ly * (1.f - lx);
        float w11 = ly * lx;
        float vy0 = (y0 >= 0 && y0 < HH) ? 1.f : 0.f;
        float vy1 = (y1 >= 0 && y1 < HH) ? 1.f : 0.f;
        float vx0 = (x0 >= 0 && x0 < WW) ? 1.f : 0.f;
        float vx1 = (x1 >= 0 && x1 < WW) ? 1.f : 0.f;
        w00 *= vy0 * vx0; w01 *= vy0 * vx1;
        w10 *= vy1 * vx0; w11 *= vy1 * vx1;
        int yc0 = min(max(y0, 0), HH - 1);
        int yc1 = min(max(y1, 0), HH - 1);
        int xc0 = min(max(x0, 0), WW - 1);
        int xc1 = min(max(x1, 0), WW - 1);
        int4 bs;   // BYTE offsets into fp16 image (row = 128 B)
        bs.x = (yc0 * WW + xc0) << 7;
        bs.y = (yc0 * WW + xc1) << 7;
        bs.z = (yc1 * WW + xc0) << 7;
        bs.w = (yc1 * WW + xc1) << 7;
        ssb[bf * 128 + t] = bs;
        uint32_t wlo, whi;
        asm("cvt.rn.f16x2.f32 %0, %1, %2;" : "=r"(wlo) : "f"(w01), "f"(w00));
        asm("cvt.rn.f16x2.f32 %0, %1, %2;" : "=r"(whi) : "f"(w11), "f"(w10));
        ssw[bf * 128 + t] = make_uint2(wlo, whi);
    };

    const uint32_t smB_u = smem_u32(smc + SM_B0);

    // prime: cp.async B(0) -> ring buf 0 (8 KB = 512 x 16 B)
    {
        const char* src = (const char*)g_wfragB;
        cp16(smB_u + t * 16, src + t * 16);
        asm volatile("cp.async.commit_group;" ::: "memory");
    }
    coords(0, 0);
    __syncthreads();   // ssb0/ssw0 ready

    const uint32_t smA_u = smem_u32(smc);
    const int m0    = (wid & 7) * 16;
    const int jbase = (wid >> 3) * 4;
    const uint32_t ldsm_lane_off = (uint32_t)((lane & 15)) * A_STRIDE + ((lane >> 4) << 4);

    float acc[4][4];
#pragma unroll
    for (int j = 0; j < 4; j++)
#pragma unroll
        for (int i = 0; i < 4; i++) acc[j][i] = 0.f;

    const int lc8  = t & 7;    // channel octet (16 B fp16)
    const int gg64 = t >> 3;   // 0..63
    int rb = 0;                // ring slot of B(k)

#pragma unroll 1
    for (int k = 0; k < 9; k++) {
        const int bf = k & 1;

        // ---- gather tap k (fp16) into A[bf]: 2 pixels/thread ----
        {
            const int4*  sbp = ssb + bf * 128;
            const uint2* swp = ssw + bf * 128;
            char* Ab = smc + (bf ? SM_A1 : SM_A0);
#pragma unroll
            for (int it = 0; it < 2; it++) {
                int p = it * 64 + gg64;
                int4  bs = sbp[p];
                uint2 wv = swp[p];
                uint32_t u00 = __byte_perm(wv.x, 0, 0x1010);
                uint32_t u01 = __byte_perm(wv.x, 0, 0x3232);
                uint32_t u10 = __byte_perm(wv.y, 0, 0x1010);
                uint32_t u11 = __byte_perm(wv.y, 0, 0x3232);
                __half2 H00 = *(__half2*)&u00, H01 = *(__half2*)&u01;
                __half2 H10 = *(__half2*)&u10, H11 = *(__half2*)&u11;
                uint4 v0 = *(const uint4*)(xhimg + bs.x + lc8 * 16);
                uint4 v1 = *(const uint4*)(xhimg + bs.y + lc8 * 16);
                uint4 v2 = *(const uint4*)(xhimg + bs.z + lc8 * 16);
                uint4 v3 = *(const uint4*)(xhimg + bs.w + lc8 * 16);
                uint4 gv;
                {
                    __half2 a;
                    a = __hmul2(*(__half2*)&v0.x, H00);
                    a = __hfma2(*(__half2*)&v1.x, H01, a);
                    a = __hfma2(*(__half2*)&v2.x, H10, a);
                    a = __hfma2(*(__half2*)&v3.x, H11, a);
                    gv.x = *(uint32_t*)&a;
                    a = __hmul2(*(__half2*)&v0.y, H00);
                    a = __hfma2(*(__half2*)&v1.y, H01, a);
                    a = __hfma2(*(__half2*)&v2.y, H10, a);
                    a = __hfma2(*(__half2*)&v3.y, H11, a);
                    gv.y = *(uint32_t*)&a;
                    a = __hmul2(*(__half2*)&v0.z, H00);
                    a = __hfma2(*(__half2*)&v1.z, H01, a);
                    a = __hfma2(*(__half2*)&v2.z, H10, a);
                    a = __hfma2(*(__half2*)&v3.z, H11, a);
                    gv.z = *(uint32_t*)&a;
                    a = __hmul2(*(__half2*)&v0.w, H00);
                    a = __hfma2(*(__half2*)&v1.w, H01, a);
                    a = __hfma2(*(__half2*)&v2.w, H10, a);
                    a = __hfma2(*(__half2*)&v3.w, H11, a);
                    gv.w = *(uint32_t*)&a;
                }
                *(uint4*)(Ab + p * A_STRIDE + lc8 * 16) = gv;
            }
        }

        // ---- coords for tap k+1 ----
        if (k < 8) coords(k + 1, bf ^ 1);

        // ---- cp.async B(k+1) into ring slot (rb+1)%3 ----
        if (k < 8) {
            int nb = rb + 1; if (nb == 3) nb = 0;
            const char* src = (const char*)(g_wfragB + (size_t)(k + 1) * 1024);
            cp16(smB_u + (uint32_t)nb * 8192 + t * 16, src + t * 16);
        }
        asm volatile("cp.async.commit_group;" ::: "memory");
        asm volatile("cp.async.wait_group 1;" ::: "memory");   // B(k) complete
        __syncthreads();   // A[bf] ready; everyone past MMA(k-1)

        // ---- tensor phase: 4 ldmatrix.x4 (A) + B LDS + 16 HMMA ----
        {
            const uint32_t abase = smA_u + (uint32_t)(bf ? SM_A1 : SM_A0) +
                                   (uint32_t)m0 * A_STRIDE + ldsm_lane_off;
            uint32_t a[4][4];
#pragma unroll
            for (int q = 0; q < 4; q++) ldsm_x4(a[q], abase + q * 32);
            const uint2* bp = (const uint2*)(smc + SM_B0 + rb * 8192) + lane;
#pragma unroll
            for (int jj = 0; jj < 4; jj++) {
                int j = jbase + jj;
                uint2 bfr[4];
#pragma unroll
                for (int q = 0; q < 4; q++) bfr[q] = bp[(j * 4 + q) * 32];
#pragma unroll
                for (int q = 0; q < 4; q++) mma16816(acc[jj], a[q], bfr[q]);
            }
        }
        rb = rb + 1; if (rb == 3) rb = 0;
    }

    // ===================== epilogue: smem-staged coalesced store =====================
    __syncthreads();
    {
        float* sout = (float*)smc;   // [64][132] floats = 33792 B (overlaps A)
        int pxa = m0 + (lane >> 2);
#pragma unroll
        for (int jj = 0; jj < 4; jj++) {
            int o = (jbase + jj) * 8 + (lane & 3) * 2;
            sout[o * 132 + pxa]           = acc[jj][0];
            sout[(o + 1) * 132 + pxa]     = acc[jj][1];
            sout[o * 132 + pxa + 8]       = acc[jj][2];
            sout[(o + 1) * 132 + pxa + 8] = acc[jj][3];
        }
        __syncthreads();
#pragma unroll
        for (int it = 0; it < 4; it++) {
            int idx = it * 512 + t;
            int o = idx >> 5, pxq = idx & 31;
            float4 vv = *(const float4*)(sout + o * 132 + pxq * 4);
            *(float4*)(out + ((size_t)(b * CC + o) * HH + h) * WW + pxq * 4) = vv;
        }
    }
}

// ---------------------------------------------------------------------------
extern "C" void kernel_launch(void* const* d_in, const int* in_sizes, int n_in,
                              void* d_out, int out_size) {
    const float* x     = (const float*)d_in[0];
    const float* wmain = (const float*)d_in[1];
    const float* wrot  = (const float*)d_in[2];
    const float* brot  = (const float*)d_in[3];
    const float* wstr  = (const float*)d_in[4];
    const float* bstr  = (const float*)d_in[5];
    const float* wwhl  = (const float*)d_in[6];
    const float* bwhl  = (const float*)d_in[7];
    float* out = (float*)d_out;

    cudaFuncSetAttribute(k_main, cudaFuncAttributeMaxDynamicSharedMemorySize, SMEM_REQ);

    k_xform<<<BB * HH, 256>>>(x, wmain, wrot, brot, wstr, bstr, wwhl, bwhl);
    k_main<<<BB * HH, 512, SMEM_REQ>>>(out);
}

// round 12
// speedup vs baseline: 1.6779x; 1.0692x over previous
#include <cuda_runtime.h>
#include <cuda_fp16.h>
#include <math.h>
#include <stdint.h>

#define BB 8
#define HH 128
#define WW 128
#define CC 64

// ---------------- scratch (allocation-free rule) ----------------
__device__ __align__(16) __half g_xh[BB*HH*WW*CC];      // NHWC x fp16 (gather)
__device__ __align__(16) uint2  g_wfragB[9*8*4*32];     // mma B-fragments fp16
__device__ __align__(16) float4 g_coef[BB*HH*WW];       // (sin, cos, wr*r, wr)

// ---------------- smem layout of k_main (dynamic, bytes) ----------------
#define A_STRIDE 144
#define SM_A0   0
#define SM_A1   18432
#define SM_B0   36864          // [3][8192] triple-buffered B ring
#define SM_SSB  61440          // int4[2][128]
#define SM_SSW  65536          // uint2[2][128]
#define SMEM_REQ 67584

// ---------------- helpers ----------------
__device__ __forceinline__ uint32_t smem_u32(const void* p) {
    uint32_t a;
    asm("{ .reg .u64 t; cvta.to.shared.u64 t, %1; cvt.u32.u64 %0, t; }" : "=r"(a) : "l"(p));
    return a;
}
__device__ __forceinline__ void ldsm_x4(uint32_t* r, uint32_t addr) {
    asm volatile("ldmatrix.sync.aligned.m8n8.x4.shared.b16 {%0,%1,%2,%3}, [%4];"
                 : "=r"(r[0]), "=r"(r[1]), "=r"(r[2]), "=r"(r[3]) : "r"(addr));
}
__device__ __forceinline__ void mma16816(float* d, const uint32_t* a, uint2 b) {
    asm volatile(
        "mma.sync.aligned.m16n8k16.row.col.f32.f16.f16.f32 "
        "{%0,%1,%2,%3}, {%4,%5,%6,%7}, {%8,%9}, {%0,%1,%2,%3};"
        : "+f"(d[0]), "+f"(d[1]), "+f"(d[2]), "+f"(d[3])
        : "r"(a[0]), "r"(a[1]), "r"(a[2]), "r"(a[3]), "r"(b.x), "r"(b.y));
}
__device__ __forceinline__ void cp16(uint32_t smem_dst, const void* gsrc) {
    asm volatile("cp.async.ca.shared.global [%0], [%1], 16;"
                 :: "r"(smem_dst), "l"(gsrc) : "memory");
}
// packed fp32x2 FMA (Blackwell): d = a * b + d, componentwise
__device__ __forceinline__ void ffma2(uint64_t& d, uint64_t a, uint64_t b) {
    asm("fma.rn.f32x2 %0, %1, %2, %0;" : "+l"(d) : "l"(a), "l"(b));
}
__device__ __forceinline__ uint64_t bcast2(float v) {
    uint64_t r;
    asm("mov.b64 %0, {%1, %1};" : "=l"(r) : "f"(v));
    return r;
}
__device__ __forceinline__ uint64_t pack2(float lo, float hi) {
    uint64_t r;
    asm("mov.b64 %0, {%1, %2};" : "=l"(r) : "f"(lo), "f"(hi));
    return r;
}
__device__ __forceinline__ void unpack2(uint64_t v, float& lo, float& hi) {
    asm("mov.b64 {%0, %1}, %2;" : "=f"(lo), "=f"(hi) : "l"(v));
}

// ---------------------------------------------------------------------------
// K1: fused weight prep + coef convs (shfl-stencil, FFMA2) + fp16 transpose
// CTA = one (b,h) row, 256 threads / 8 warps.
// Warp w = channels w*8..w*8+7; lane l = pixels 4l..4l+3 (full row).
// Per (ch, dy): ONE LDG.128 + 2 shfl builds all 3 shifted taps.
// ---------------------------------------------------------------------------
#define SXH2_STRIDE 136   // halves per channel row (8B-aligned stride)

__global__ void __launch_bounds__(256) k_xform(const float* __restrict__ x,
                                               const float* __restrict__ wmain,
                                               const float* __restrict__ wrot,
                                               const float* __restrict__ brot,
                                               const float* __restrict__ wstr,
                                               const float* __restrict__ bstr,
                                               const float* __restrict__ wwhl,
                                               const float* __restrict__ bwhl) {
    __shared__ float4 swc[CC * 9];                         // [c][tap] -> 4 outs
    __shared__ float4 red[8 * 128];                        // [warp][px] partials
    __shared__ __align__(16) __half sxh2[CC][SXH2_STRIDE]; // [c][px] staging

    const int t    = threadIdx.x;
    const int lane = t & 31;
    const int w    = t >> 5;
    const int bh   = blockIdx.x;
    const int b    = bh >> 7;
    const int h    = bh & 127;

    // ---- B-fragment prep slice (independent; before any sync) ----
    if (t < 36) {
        int idx = bh * 36 + t;
        int k = idx % 9;
        int c = (idx / 9) % CC;
        int o = idx / (9 * CC);
        float wv = wmain[idx];
        int j = o >> 3, lane_n = o & 7;
        int q = c >> 4, kk = c & 15;
        int reg = kk >> 3, r = kk & 7;
        int ln = lane_n * 4 + (r >> 1);
        int halfsel = r & 1;
        __half* dst = (__half*)g_wfragB;
        dst[(((size_t)(k * 8 + j) * 4 + q) * 32 + ln) * 4 + reg * 2 + halfsel] = __float2half(wv);
    }

    // ---- coef weights: swc[c*9+tap] ----
    for (int i = t; i < CC * 9; i += 256) {
        int c = i / 9, tap = i - c * 9;
        swc[i] = make_float4(wrot[(0 * CC + c) * 9 + tap],
                             wrot[(1 * CC + c) * 9 + tap],
                             wstr[c * 9 + tap],
                             wwhl[c * 9 + tap]);
    }
    __syncthreads();

    // ---- stencil conv: acc[out][px-pair], px pairs (4l,4l+1) and (4l+2,4l+3)
    uint64_t acc[4][2];
#pragma unroll
    for (int o = 0; o < 4; o++) { acc[o][0] = 0ull; acc[o][1] = 0ull; }

    const float* xb = x + (size_t)(b * CC + w * 8) * (HH * WW);
#pragma unroll
    for (int cc = 0; cc < 8; cc++) {
        int c = w * 8 + cc;
        const float* xc = xb + (size_t)cc * (HH * WW);
        const float4* wcp = swc + c * 9;
#pragma unroll
        for (int dy = 0; dy < 3; dy++) {
            int y = h + dy - 1;
            if ((unsigned)y >= HH) continue;   // warp-uniform
            float4 C = *(const float4*)(xc + y * WW + lane * 4);
            if (dy == 1) {
                uint32_t h01, h23;
                asm("cvt.rn.f16x2.f32 %0, %1, %2;" : "=r"(h01) : "f"(C.y), "f"(C.x));
                asm("cvt.rn.f16x2.f32 %0, %1, %2;" : "=r"(h23) : "f"(C.w), "f"(C.z));
                *(uint2*)&sxh2[c][lane * 4] = make_uint2(h01, h23);
            }
            float up = __shfl_up_sync(0xffffffffu, C.w, 1);
            float dn = __shfl_down_sync(0xffffffffu, C.x, 1);
            if (lane == 0)  up = 0.f;   // image left boundary
            if (lane == 31) dn = 0.f;   // image right boundary
            uint64_t xm01 = pack2(up, C.x),  xm23 = pack2(C.y, C.z);
            uint64_t x001 = pack2(C.x, C.y), x023 = pack2(C.z, C.w);
            uint64_t xp01 = pack2(C.y, C.z), xp23 = pack2(C.w, dn);
            float4 wA = wcp[dy * 3 + 0];
            float4 wB = wcp[dy * 3 + 1];
            float4 wC = wcp[dy * 3 + 2];
#pragma unroll
            for (int o = 0; o < 4; o++) {
                float wa = (o == 0) ? wA.x : (o == 1) ? wA.y : (o == 2) ? wA.z : wA.w;
                float wb = (o == 0) ? wB.x : (o == 1) ? wB.y : (o == 2) ? wB.z : wB.w;
                float wc = (o == 0) ? wC.x : (o == 1) ? wC.y : (o == 2) ? wC.z : wC.w;
                uint64_t ba = bcast2(wa), bb = bcast2(wb), bc = bcast2(wc);
                ffma2(acc[o][0], xm01, ba);
                ffma2(acc[o][0], x001, bb);
                ffma2(acc[o][0], xp01, bc);
                ffma2(acc[o][1], xm23, ba);
                ffma2(acc[o][1], x023, bb);
                ffma2(acc[o][1], xp23, bc);
            }
        }
    }

    // ---- write per-warp partials ----
    {
        float e[4][4];   // [out][i]
#pragma unroll
        for (int o = 0; o < 4; o++) {
            unpack2(acc[o][0], e[o][0], e[o][1]);
            unpack2(acc[o][1], e[o][2], e[o][3]);
        }
        float4* redp = red + w * 128 + lane * 4;
#pragma unroll
        for (int i = 0; i < 4; i++)
            redp[i] = make_float4(e[0][i], e[1][i], e[2][i], e[3][i]);
    }
    __syncthreads();   // red + sxh2 complete

    if (t < 128) {
        float a0 = 0.f, a1 = 0.f, a2 = 0.f, a3 = 0.f;
#pragma unroll
        for (int ww = 0; ww < 8; ww++) {
            float4 u = red[ww * 128 + t];
            a0 += u.x; a1 += u.y; a2 += u.z; a3 += u.w;
        }
        float s = a0 + brot[0];
        float c = a1 + brot[1];
        float n = sqrtf(s * s + c * c + 1e-6f);
        s /= n; c /= n;
        float r  = tanhf(a2 + bstr[0]) * 1.25f + 1.75f;
        float wl = tanhf(a3 + bwhl[0]) * 1.0f + 2.0f;
        g_coef[bh * WW + t] = make_float4(s, c, wl * r, wl);
    }

    // ---- coalesced fp16 NHWC writeout: sxh2[c][px] -> g_xh[px][c] ----
    {
        __half* gdst = g_xh + (size_t)bh * WW * CC;
#pragma unroll
        for (int it = 0; it < 4; it++) {
            int idx = it * 256 + t;
            int px = idx >> 3, c8 = idx & 7;
            __half hv[8];
#pragma unroll
            for (int j = 0; j < 8; j++) hv[j] = sxh2[c8 * 8 + j][px];
            *(uint4*)(gdst + px * CC + c8 * 8) = *(uint4*)hv;
        }
    }
}

// ---------------------------------------------------------------------------
// K2: deform gather (fp16) + mma.sync GEMM  (unchanged from R11)
// CTA = one (b,h) row (128 px), 512 threads / 16 warps, 2 CTAs/SM.
// ---------------------------------------------------------------------------
__global__ void __launch_bounds__(512, 2) k_main(float* __restrict__ out) {
    extern __shared__ __align__(16) char smc[];
    int4*  ssb = (int4*)(smc + SM_SSB);    // [2][128]
    uint2* ssw = (uint2*)(smc + SM_SSW);   // [2][128]

    const int t    = threadIdx.x;
    const int wid  = t >> 5;
    const int lane = t & 31;
    const int bh   = blockIdx.x;
    const int b    = bh >> 7;
    const int h    = bh & 127;
    const char* xhimg = (const char*)(g_xh + (size_t)b * HH * WW * CC);

    float4 cf;
    if (t < 128) cf = g_coef[bh * WW + t];

    auto coords = [&](int k, int bf) {
        if (t >= 128) return;
        int kd3 = (k * 11) >> 5;
        float ky = (float)(kd3 - 1);
        float kx = (float)(k - 3 * kd3 - 1);
        float o0 = ky * cf.z;
        float o1 = kx * cf.w;
        float py = (float)h + cf.y * o0 + cf.x * o1;
        float px = (float)t - cf.x * o0 + cf.y * o1;
        float yf = floorf(py), xf = floorf(px);
        float ly = py - yf, lx = px - xf;
        int y0 = (int)yf, x0 = (int)xf;
        int y1 = y0 + 1,  x1 = x0 + 1;
        float w00 = (1.f - ly) * (1.f - lx);
        float w01 = (1.f - ly) * lx;
        float w10 = ly * (1.f - lx);
        float w11 = ly * lx;
        float vy0 = (y0 >= 0 && y0 < HH) ? 1.f : 0.f;
        float vy1 = (y1 >= 0 && y1 < HH) ? 1.f : 0.f;
        float vx0 = (x0 >= 0 && x0 < WW) ? 1.f : 0.f;
        float vx1 = (x1 >= 0 && x1 < WW) ? 1.f : 0.f;
        w00 *= vy0 * vx0; w01 *= vy0 * vx1;
        w10 *= vy1 * vx0; w11 *= vy1 * vx1;
        int yc0 = min(max(y0, 0), HH - 1);
        int yc1 = min(max(y1, 0), HH - 1);
        int xc0 = min(max(x0, 0), WW - 1);
        int xc1 = min(max(x1, 0), WW - 1);
        int4 bs;   // BYTE offsets into fp16 image (row = 128 B)
        bs.x = (yc0 * WW + xc0) << 7;
        bs.y = (yc0 * WW + xc1) << 7;
        bs.z = (yc1 * WW + xc0) << 7;
        bs.w = (yc1 * WW + xc1) << 7;
        ssb[bf * 128 + t] = bs;
        uint32_t wlo, whi;
        asm("cvt.rn.f16x2.f32 %0, %1, %2;" : "=r"(wlo) : "f"(w01), "f"(w00));
        asm("cvt.rn.f16x2.f32 %0, %1, %2;" : "=r"(whi) : "f"(w11), "f"(w10));
        ssw[bf * 128 + t] = make_uint2(wlo, whi);
    };

    const uint32_t smB_u = smem_u32(smc + SM_B0);

    // prime: cp.async B(0) -> ring buf 0 (8 KB = 512 x 16 B)
    {
        const char* src = (const char*)g_wfragB;
        cp16(smB_u + t * 16, src + t * 16);
        asm volatile("cp.async.commit_group;" ::: "memory");
    }
    coords(0, 0);
    __syncthreads();   // ssb0/ssw0 ready

    const uint32_t smA_u = smem_u32(smc);
    const int m0    = (wid & 7) * 16;
    const int jbase = (wid >> 3) * 4;
    const uint32_t ldsm_lane_off = (uint32_t)((lane & 15)) * A_STRIDE + ((lane >> 4) << 4);

    float acc[4][4];
#pragma unroll
    for (int j = 0; j < 4; j++)
#pragma unroll
        for (int i = 0; i < 4; i++) acc[j][i] = 0.f;

    const int lc8  = t & 7;    // channel octet (16 B fp16)
    const int gg64 = t >> 3;   // 0..63
    int rb = 0;                // ring slot of B(k)

#pragma unroll 1
    for (int k = 0; k < 9; k++) {
        const int bf = k & 1;

        // ---- gather tap k (fp16) into A[bf]: 2 pixels/thread ----
        {
            const int4*  sbp = ssb + bf * 128;
            const uint2* swp = ssw + bf * 128;
            char* Ab = smc + (bf ? SM_A1 : SM_A0);
#pragma unroll
            for (int it = 0; it < 2; it++) {
                int p = it * 64 + gg64;
                int4  bs = sbp[p];
                uint2 wv = swp[p];
                uint32_t u00 = __byte_perm(wv.x, 0, 0x1010);
                uint32_t u01 = __byte_perm(wv.x, 0, 0x3232);
                uint32_t u10 = __byte_perm(wv.y, 0, 0x1010);
                uint32_t u11 = __byte_perm(wv.y, 0, 0x3232);
                __half2 H00 = *(__half2*)&u00, H01 = *(__half2*)&u01;
                __half2 H10 = *(__half2*)&u10, H11 = *(__half2*)&u11;
                uint4 v0 = *(const uint4*)(xhimg + bs.x + lc8 * 16);
                uint4 v1 = *(const uint4*)(xhimg + bs.y + lc8 * 16);
                uint4 v2 = *(const uint4*)(xhimg + bs.z + lc8 * 16);
                uint4 v3 = *(const uint4*)(xhimg + bs.w + lc8 * 16);
                uint4 gv;
                {
                    __half2 a;
                    a = __hmul2(*(__half2*)&v0.x, H00);
                    a = __hfma2(*(__half2*)&v1.x, H01, a);
                    a = __hfma2(*(__half2*)&v2.x, H10, a);
                    a = __hfma2(*(__half2*)&v3.x, H11, a);
                    gv.x = *(uint32_t*)&a;
                    a = __hmul2(*(__half2*)&v0.y, H00);
                    a = __hfma2(*(__half2*)&v1.y, H01, a);
                    a = __hfma2(*(__half2*)&v2.y, H10, a);
                    a = __hfma2(*(__half2*)&v3.y, H11, a);
                    gv.y = *(uint32_t*)&a;
                    a = __hmul2(*(__half2*)&v0.z, H00);
                    a = __hfma2(*(__half2*)&v1.z, H01, a);
                    a = __hfma2(*(__half2*)&v2.z, H10, a);
                    a = __hfma2(*(__half2*)&v3.z, H11, a);
                    gv.z = *(uint32_t*)&a;
                    a = __hmul2(*(__half2*)&v0.w, H00);
                    a = __hfma2(*(__half2*)&v1.w, H01, a);
                    a = __hfma2(*(__half2*)&v2.w, H10, a);
                    a = __hfma2(*(__half2*)&v3.w, H11, a);
                    gv.w = *(uint32_t*)&a;
                }
                *(uint4*)(Ab + p * A_STRIDE + lc8 * 16) = gv;
            }
        }

        // ---- coords for tap k+1 ----
        if (k < 8) coords(k + 1, bf ^ 1);

        // ---- cp.async B(k+1) into ring slot (rb+1)%3 ----
        if (k < 8) {
            int nb = rb + 1; if (nb == 3) nb = 0;
            const char* src = (const char*)(g_wfragB + (size_t)(k + 1) * 1024);
            cp16(smB_u + (uint32_t)nb * 8192 + t * 16, src + t * 16);
        }
        asm volatile("cp.async.commit_group;" ::: "memory");
        asm volatile("cp.async.wait_group 1;" ::: "memory");   // B(k) complete
        __syncthreads();   // A[bf] ready; everyone past MMA(k-1)

        // ---- tensor phase: 4 ldmatrix.x4 (A) + B LDS + 16 HMMA ----
        {
            const uint32_t abase = smA_u + (uint32_t)(bf ? SM_A1 : SM_A0) +
                                   (uint32_t)m0 * A_STRIDE + ldsm_lane_off;
            uint32_t a[4][4];
#pragma unroll
            for (int q = 0; q < 4; q++) ldsm_x4(a[q], abase + q * 32);
            const uint2* bp = (const uint2*)(smc + SM_B0 + rb * 8192) + lane;
#pragma unroll
            for (int jj = 0; jj < 4; jj++) {
                int j = jbase + jj;
                uint2 bfr[4];
#pragma unroll
                for (int q = 0; q < 4; q++) bfr[q] = bp[(j * 4 + q) * 32];
#pragma unroll
                for (int q = 0; q < 4; q++) mma16816(acc[jj], a[q], bfr[q]);
            }
        }
        rb = rb + 1; if (rb == 3) rb = 0;
    }

    // ===================== epilogue: smem-staged coalesced store =====================
    __syncthreads();
    {
        float* sout = (float*)smc;   // [64][132] floats = 33792 B (overlaps A)
        int pxa = m0 + (lane >> 2);
#pragma unroll
        for (int jj = 0; jj < 4; jj++) {
            int o = (jbase + jj) * 8 + (lane & 3) * 2;
            sout[o * 132 + pxa]           = acc[jj][0];
            sout[(o + 1) * 132 + pxa]     = acc[jj][1];
            sout[o * 132 + pxa + 8]       = acc[jj][2];
            sout[(o + 1) * 132 + pxa + 8] = acc[jj][3];
        }
        __syncthreads();
#pragma unroll
        for (int it = 0; it < 4; it++) {
            int idx = it * 512 + t;
            int o = idx >> 5, pxq = idx & 31;
            float4 vv = *(const float4*)(sout + o * 132 + pxq * 4);
            *(float4*)(out + ((size_t)(b * CC + o) * HH + h) * WW + pxq * 4) = vv;
        }
    }
}

// ---------------------------------------------------------------------------
extern "C" void kernel_launch(void* const* d_in, const int* in_sizes, int n_in,
                              void* d_out, int out_size) {
    const float* x     = (const float*)d_in[0];
    const float* wmain = (const float*)d_in[1];
    const float* wrot  = (const float*)d_in[2];
    const float* brot  = (const float*)d_in[3];
    const float* wstr  = (const float*)d_in[4];
    const float* bstr  = (const float*)d_in[5];
    const float* wwhl  = (const float*)d_in[6];
    const float* bwhl  = (const float*)d_in[7];
    float* out = (float*)d_out;

    cudaFuncSetAttribute(k_main, cudaFuncAttributeMaxDynamicSharedMemorySize, SMEM_REQ);

    k_xform<<<BB * HH, 256>>>(x, wmain, wrot, brot, wstr, bstr, wwhl, bwhl);
    k_main<<<BB * HH, 512, SMEM_REQ>>>(out);
}